// round 1
// baseline (speedup 1.0000x reference)
#include <cuda_runtime.h>
#include <stdint.h>

// Problem constants
#define NN 262144
#define EE (NN * 16)
#define CC 64
#define NVOXD 20
#define NVOX 8000
#define BN_EPS 1e-5f
#define GRID_INV 2.0f   // 1/0.5

// -------- scratch (device globals; zero-init only at load, so per-call zeroing kernel below) --------
__device__ float g_h[NN * CC];        // h = x@W+b, then BN+ReLU'd in-place (nonneg after)
__device__ float g_pooled[NN * CC];   // scatter-max target, init = BN-ReLU'd h (self loop)
__device__ float g_colsum[CC];
__device__ float g_colsq[CC];
__device__ float g_scale[CC];
__device__ float g_shift[CC];
__device__ float g_xsum[NVOX * CC];
__device__ float g_psum[NVOX * 3];
__device__ float g_cnt[NVOX];

// -------- 0: zero per-call accumulators --------
__global__ void zero_kernel() {
    int i = blockIdx.x * blockDim.x + threadIdx.x;
    int stride = gridDim.x * blockDim.x;
    for (int j = i; j < NVOX * CC; j += stride) g_xsum[j] = 0.f;
    for (int j = i; j < NVOX * 3; j += stride)  g_psum[j] = 0.f;
    for (int j = i; j < NVOX; j += stride)      g_cnt[j]  = 0.f;
    if (i < CC) { g_colsum[i] = 0.f; g_colsq[i] = 0.f; }
}

// -------- 1: GEMM h = x @ W + b   (64 rows per block, 256 threads) --------
__global__ __launch_bounds__(256) void gemm_kernel(const float* __restrict__ x,
                                                   const float* __restrict__ W,
                                                   const float* __restrict__ b) {
    __shared__ float Ws[64][65];
    __shared__ float xs[64][65];
    int tid = threadIdx.x;
    int row0 = blockIdx.x * 64;
#pragma unroll
    for (int i = tid; i < 4096; i += 256) Ws[i >> 6][i & 63] = W[i];
#pragma unroll
    for (int i = tid; i < 4096; i += 256) xs[i >> 6][i & 63] = x[row0 * 64 + i];
    __syncthreads();

    int r = tid >> 2;            // 0..63 local row
    int c0 = (tid & 3) * 16;     // column quad
    float acc[16];
#pragma unroll
    for (int j = 0; j < 16; j++) acc[j] = b[c0 + j];
#pragma unroll 4
    for (int k = 0; k < 64; k++) {
        float xv = xs[r][k];
#pragma unroll
        for (int j = 0; j < 16; j++) acc[j] += xv * Ws[k][c0 + j];
    }
    float* dst = &g_h[(long long)(row0 + r) * 64 + c0];
#pragma unroll
    for (int j = 0; j < 16; j += 4) {
        float4 v = make_float4(acc[j], acc[j + 1], acc[j + 2], acc[j + 3]);
        *reinterpret_cast<float4*>(dst + j) = v;
    }
}

// -------- 2: per-column sum / sumsq over h --------
__global__ __launch_bounds__(256) void stats_kernel() {
    // gridDim.x * 256 is a multiple of 64, so each thread stays on one column
    float s = 0.f, sq = 0.f;
    int stride = gridDim.x * blockDim.x;
    for (int i = blockIdx.x * blockDim.x + threadIdx.x; i < NN * CC; i += stride) {
        float v = g_h[i];
        s += v; sq += v * v;
    }
    __shared__ float ss[256], ssq[256];
    ss[threadIdx.x] = s; ssq[threadIdx.x] = sq;
    __syncthreads();
    if (threadIdx.x < 64) {
        float a  = ss[threadIdx.x] + ss[threadIdx.x + 64] + ss[threadIdx.x + 128] + ss[threadIdx.x + 192];
        float aq = ssq[threadIdx.x] + ssq[threadIdx.x + 64] + ssq[threadIdx.x + 128] + ssq[threadIdx.x + 192];
        atomicAdd(&g_colsum[threadIdx.x], a);
        atomicAdd(&g_colsq[threadIdx.x], aq);
    }
}

// -------- 3: fold BN into scale/shift --------
__global__ void scale_kernel(const float* __restrict__ gamma, const float* __restrict__ beta) {
    int c = threadIdx.x;
    if (c < CC) {
        float mean = g_colsum[c] * (1.0f / NN);
        float var = g_colsq[c] * (1.0f / NN) - mean * mean;
        float sc = gamma[c] * rsqrtf(var + BN_EPS);
        g_scale[c] = sc;
        g_shift[c] = beta[c] - mean * sc;
    }
}

// -------- 4: apply BN + ReLU in-place, and init pooled = h (self-loop) --------
__global__ __launch_bounds__(256) void bnrelu_kernel() {
    __shared__ float sc[64], sh[64];
    if (threadIdx.x < 64) { sc[threadIdx.x] = g_scale[threadIdx.x]; sh[threadIdx.x] = g_shift[threadIdx.x]; }
    __syncthreads();
    int stride = gridDim.x * blockDim.x;
    float4* h4 = reinterpret_cast<float4*>(g_h);
    float4* p4 = reinterpret_cast<float4*>(g_pooled);
    for (int i = blockIdx.x * blockDim.x + threadIdx.x; i < NN * (CC / 4); i += stride) {
        int c0 = (i * 4) & 63;
        float4 v = h4[i];
        v.x = fmaxf(fmaf(v.x, sc[c0 + 0], sh[c0 + 0]), 0.f);
        v.y = fmaxf(fmaf(v.y, sc[c0 + 1], sh[c0 + 1]), 0.f);
        v.z = fmaxf(fmaf(v.z, sc[c0 + 2], sh[c0 + 2]), 0.f);
        v.w = fmaxf(fmaf(v.w, sc[c0 + 3], sh[c0 + 3]), 0.f);
        h4[i] = v;
        p4[i] = v;
    }
}

// -------- 5: edge scatter-max (one warp per edge; uint atomicMax on nonneg floats) --------
__global__ __launch_bounds__(256) void edge_kernel(const int* __restrict__ ei) {
    int warp_id = (blockIdx.x * blockDim.x + threadIdx.x) >> 5;
    int lane = threadIdx.x & 31;
    if (warp_id >= EE) return;
    int row = __ldg(&ei[warp_id]);
    int col = __ldg(&ei[EE + warp_id]);
    const uint2* src = reinterpret_cast<const uint2*>(reinterpret_cast<const unsigned int*>(g_h) + (long long)row * 64);
    unsigned int* dst = reinterpret_cast<unsigned int*>(g_pooled) + (long long)col * 64;
    uint2 v = src[lane];
    // nonneg IEEE floats compare identically as uints; zeros can't raise the max (pooled >= 0)
    if (v.x) atomicMax(dst + 2 * lane, v.x);
    if (v.y) atomicMax(dst + 2 * lane + 1, v.y);
}

// -------- 6: voxel scatter (one warp per node) --------
__global__ __launch_bounds__(256) void voxel_kernel(const float* __restrict__ pos) {
    int node = (blockIdx.x * blockDim.x + threadIdx.x) >> 5;
    int lane = threadIdx.x & 31;
    if (node >= NN) return;
    float px = 0.f, py = 0.f, pz = 0.f;
    int vox = 0;
    if (lane == 0) {
        px = pos[node * 3 + 0];
        py = pos[node * 3 + 1];
        pz = pos[node * 3 + 2];
        int vx = (int)floorf(px * GRID_INV);
        int vy = (int)floorf(py * GRID_INV);
        int vz = (int)floorf(pz * GRID_INV);
        vx = min(max(vx, 0), NVOXD - 1);
        vy = min(max(vy, 0), NVOXD - 1);
        vz = min(max(vz, 0), NVOXD - 1);
        vox = (vx * NVOXD + vy) * NVOXD + vz;
    }
    vox = __shfl_sync(0xFFFFFFFFu, vox, 0);
    const float2* src = reinterpret_cast<const float2*>(g_pooled + (long long)node * 64);
    float2 v = src[lane];
    float* xbase = &g_xsum[(long long)vox * 64];
    atomicAdd(xbase + 2 * lane, v.x);
    atomicAdd(xbase + 2 * lane + 1, v.y);
    if (lane == 0) {
        atomicAdd(&g_cnt[vox], 1.0f);
        atomicAdd(&g_psum[vox * 3 + 0], px);
        atomicAdd(&g_psum[vox * 3 + 1], py);
        atomicAdd(&g_psum[vox * 3 + 2], pz);
    }
}

// -------- 7: finalize output [NVOX, 67] --------
__global__ void out_kernel(float* __restrict__ out) {
    int i = blockIdx.x * blockDim.x + threadIdx.x;
    if (i >= NVOX * 67) return;
    int v = i / 67;
    int c = i - v * 67;
    float denom = fmaxf(g_cnt[v], 1.0f);
    float val = (c < 64) ? g_xsum[v * 64 + c] : g_psum[v * 3 + (c - 64)];
    out[i] = val / denom;
}

extern "C" void kernel_launch(void* const* d_in, const int* in_sizes, int n_in,
                              void* d_out, int out_size) {
    const float* x     = (const float*)d_in[0];  // [N, 64]
    const float* pos   = (const float*)d_in[1];  // [N, 3]
    const int*   ei    = (const int*)d_in[2];    // [2, E]
    const float* W     = (const float*)d_in[3];  // [64, 64]
    const float* b     = (const float*)d_in[4];  // [64]
    const float* gamma = (const float*)d_in[5];  // [64]
    const float* beta  = (const float*)d_in[6];  // [64]
    float* out = (float*)d_out;                  // [8000, 67]

    zero_kernel<<<512, 256>>>();
    gemm_kernel<<<NN / 64, 256>>>(x, W, b);
    stats_kernel<<<1024, 256>>>();
    scale_kernel<<<1, 64>>>(gamma, beta);
    bnrelu_kernel<<<4096, 256>>>();
    edge_kernel<<<EE / 8, 256>>>(ei);           // 1 warp per edge
    voxel_kernel<<<NN / 8, 256>>>(pos);          // 1 warp per node
    out_kernel<<<(NVOX * 67 + 255) / 256, 256>>>(out);
}

// round 2
// speedup vs baseline: 2.3069x; 2.3069x over previous
#include <cuda_runtime.h>
#include <stdint.h>

// Problem constants
#define NN 262144
#define EE (NN * 16)
#define CC 64
#define NVOXD 20
#define NVOX 8000
#define BN_EPS 1e-5f
#define GRID_INV 2.0f   // 1/0.5
#define FULLMASK 0xFFFFFFFFu

// -------- scratch --------
__device__ float g_h[NN * CC];            // raw h = x@W+b (BN applied on the fly later)
__device__ float g_colsum[CC];
__device__ float g_colsq[CC];
__device__ float g_scale[CC];
__device__ float g_shift[CC];
__device__ float g_xsum[NVOX * CC];
__device__ float g_psum[NVOX * 3];
__device__ float g_cnt[NVOX];
__device__ int   g_cnt_i[NN];             // in-degree per node
__device__ int   g_off[NN];               // CSR offsets
__device__ int   g_cur[NN];               // scatter cursors
__device__ int   g_adj[EE];               // CSR adjacency (source rows per dest)
__device__ int   g_total;                 // global offset counter

// -------- 0: zero per-call accumulators --------
__global__ void zero_kernel() {
    int i = blockIdx.x * blockDim.x + threadIdx.x;
    int stride = gridDim.x * blockDim.x;
    for (int j = i; j < NVOX * CC; j += stride) g_xsum[j] = 0.f;
    for (int j = i; j < NVOX * 3; j += stride)  g_psum[j] = 0.f;
    for (int j = i; j < NVOX; j += stride)      g_cnt[j]  = 0.f;
    for (int j = i; j < NN; j += stride)        g_cnt_i[j] = 0;
    if (i < CC) { g_colsum[i] = 0.f; g_colsq[i] = 0.f; }
    if (i == 0) g_total = 0;
}

// -------- 1: GEMM h = x @ W + b  (64 rows/block, 256 thr, f32x2 FFMA) --------
// Thread (r = tid>>2, q = tid&3) computes row r, column pairs p = q + 4*j (j=0..7),
// i.e. columns {2p, 2p+1}. Per-warp Ws addresses for fixed j are 4 consecutive 8B
// words -> conflict-free LDS.64 broadcast, no padding needed on Ws.
__global__ __launch_bounds__(256) void gemm_kernel(const float* __restrict__ x,
                                                   const float* __restrict__ W,
                                                   const float* __restrict__ b) {
    __shared__ float Ws[64 * 64];      // row stride 64 floats (256B, 8B-aligned)
    __shared__ float xs[64][65];       // odd stride: conflict-free across rows
    int tid = threadIdx.x;
    int row0 = blockIdx.x * 64;
#pragma unroll
    for (int i = tid; i < 4096; i += 256) Ws[i] = W[i];
#pragma unroll
    for (int i = tid; i < 4096; i += 256) xs[i >> 6][i & 63] = x[row0 * 64 + i];
    __syncthreads();

    int r = tid >> 2;
    int q = tid & 3;

    unsigned long long acc[8];
#pragma unroll
    for (int j = 0; j < 8; j++) {
        int p = q + 4 * j;
        unsigned int lo = __float_as_uint(b[2 * p]);
        unsigned int hi = __float_as_uint(b[2 * p + 1]);
        acc[j] = (unsigned long long)lo | ((unsigned long long)hi << 32);
    }

#pragma unroll 4
    for (int k = 0; k < 64; k++) {
        float xv = xs[r][k];
        unsigned int xu = __float_as_uint(xv);
        unsigned long long xvv;
        asm("mov.b64 %0, {%1, %1};" : "=l"(xvv) : "r"(xu));
        const unsigned long long* wrow =
            reinterpret_cast<const unsigned long long*>(&Ws[k * 64]);
#pragma unroll
        for (int j = 0; j < 8; j++) {
            unsigned long long w = wrow[q + 4 * j];
            asm("fma.rn.f32x2 %0, %1, %2, %0;" : "+l"(acc[j]) : "l"(w), "l"(xvv));
        }
    }

    unsigned long long* dst =
        reinterpret_cast<unsigned long long*>(&g_h[(long long)(row0 + r) * 64]);
#pragma unroll
    for (int j = 0; j < 8; j++) dst[q + 4 * j] = acc[j];
}

// -------- 2: per-column sum / sumsq over raw h --------
__global__ __launch_bounds__(256) void stats_kernel() {
    float s = 0.f, sq = 0.f;
    int stride = gridDim.x * blockDim.x;      // multiple of 64 -> fixed column per thread
    for (int i = blockIdx.x * blockDim.x + threadIdx.x; i < NN * CC; i += stride) {
        float v = g_h[i];
        s += v; sq += v * v;
    }
    __shared__ float ss[256], ssq[256];
    ss[threadIdx.x] = s; ssq[threadIdx.x] = sq;
    __syncthreads();
    if (threadIdx.x < 64) {
        float a  = ss[threadIdx.x] + ss[threadIdx.x + 64] + ss[threadIdx.x + 128] + ss[threadIdx.x + 192];
        float aq = ssq[threadIdx.x] + ssq[threadIdx.x + 64] + ssq[threadIdx.x + 128] + ssq[threadIdx.x + 192];
        atomicAdd(&g_colsum[threadIdx.x], a);
        atomicAdd(&g_colsq[threadIdx.x], aq);
    }
}

// -------- 3: fold BN into scale/shift --------
__global__ void scale_kernel(const float* __restrict__ gamma, const float* __restrict__ beta) {
    int c = threadIdx.x;
    if (c < CC) {
        float mean = g_colsum[c] * (1.0f / NN);
        float var = g_colsq[c] * (1.0f / NN) - mean * mean;
        float sc = gamma[c] * rsqrtf(var + BN_EPS);
        g_scale[c] = sc;
        g_shift[c] = beta[c] - mean * sc;
    }
}

// -------- 4: in-degree histogram --------
__global__ __launch_bounds__(256) void hist_kernel(const int* __restrict__ ei) {
    int e = blockIdx.x * blockDim.x + threadIdx.x;
    if (e < EE) atomicAdd(&g_cnt_i[ei[EE + e]], 1);
}

// -------- 5: offsets via warp-aggregated atomic (order-free CSR grouping) --------
__global__ __launch_bounds__(256) void offset_kernel() {
    int i = blockIdx.x * blockDim.x + threadIdx.x;
    int lane = threadIdx.x & 31;
    int c = g_cnt_i[i];
    int s = c;
#pragma unroll
    for (int d = 1; d < 32; d <<= 1) {
        int t = __shfl_up_sync(FULLMASK, s, d);
        if (lane >= d) s += t;
    }
    int total = __shfl_sync(FULLMASK, s, 31);
    int base = 0;
    if (lane == 31) base = atomicAdd(&g_total, total);
    base = __shfl_sync(FULLMASK, base, 31);
    int off = base + s - c;   // exclusive prefix within warp
    g_off[i] = off;
    g_cur[i] = off;
}

// -------- 6: scatter edge sources into CSR --------
__global__ __launch_bounds__(256) void scatter_kernel(const int* __restrict__ ei) {
    int e = blockIdx.x * blockDim.x + threadIdx.x;
    if (e >= EE) return;
    int row = ei[e];
    int col = ei[EE + e];
    int p = atomicAdd(&g_cur[col], 1);
    g_adj[p] = row;
}

// -------- 7: fused gather-max (BN+ReLU on the fly) + voxel scatter --------
__global__ __launch_bounds__(256) void gather_kernel(const float* __restrict__ pos) {
    int node = (blockIdx.x * blockDim.x + threadIdx.x) >> 5;
    int lane = threadIdx.x & 31;
    if (node >= NN) return;

    float scx = g_scale[2 * lane], scy = g_scale[2 * lane + 1];
    float shx = g_shift[2 * lane], shy = g_shift[2 * lane + 1];

    const float2* h2 = reinterpret_cast<const float2*>(g_h);
    // self value (with ReLU). Since a,b >= 0 afterwards, max with raw BN values
    // of neighbors is identical to max with their ReLU'd values.
    float2 v = h2[(long long)node * 32 + lane];
    float a = fmaxf(fmaf(v.x, scx, shx), 0.f);
    float bb = fmaxf(fmaf(v.y, scy, shy), 0.f);

    int off = g_off[node];
    int cnt = g_cnt_i[node];
    for (int j0 = 0; j0 < cnt; j0 += 32) {
        int idx = (j0 + lane < cnt) ? g_adj[off + j0 + lane] : 0;
        int m = min(32, cnt - j0);
        for (int t = 0; t < m; t++) {
            int src = __shfl_sync(FULLMASK, idx, t);
            float2 u = h2[(long long)src * 32 + lane];
            a  = fmaxf(a,  fmaf(u.x, scx, shx));
            bb = fmaxf(bb, fmaf(u.y, scy, shy));
        }
    }

    // voxel id
    float px = 0.f, py = 0.f, pz = 0.f;
    int vox = 0;
    if (lane == 0) {
        px = pos[node * 3 + 0];
        py = pos[node * 3 + 1];
        pz = pos[node * 3 + 2];
        int vx = min(max((int)floorf(px * GRID_INV), 0), NVOXD - 1);
        int vy = min(max((int)floorf(py * GRID_INV), 0), NVOXD - 1);
        int vz = min(max((int)floorf(pz * GRID_INV), 0), NVOXD - 1);
        vox = (vx * NVOXD + vy) * NVOXD + vz;
    }
    vox = __shfl_sync(FULLMASK, vox, 0);

    float* xbase = &g_xsum[(long long)vox * 64];
    atomicAdd(xbase + 2 * lane, a);
    atomicAdd(xbase + 2 * lane + 1, bb);
    if (lane == 0) {
        atomicAdd(&g_cnt[vox], 1.0f);
        atomicAdd(&g_psum[vox * 3 + 0], px);
        atomicAdd(&g_psum[vox * 3 + 1], py);
        atomicAdd(&g_psum[vox * 3 + 2], pz);
    }
}

// -------- 8: finalize output [NVOX, 67] --------
__global__ void out_kernel(float* __restrict__ out) {
    int i = blockIdx.x * blockDim.x + threadIdx.x;
    if (i >= NVOX * 67) return;
    int v = i / 67;
    int c = i - v * 67;
    float denom = fmaxf(g_cnt[v], 1.0f);
    float val = (c < 64) ? g_xsum[v * 64 + c] : g_psum[v * 3 + (c - 64)];
    out[i] = val / denom;
}

extern "C" void kernel_launch(void* const* d_in, const int* in_sizes, int n_in,
                              void* d_out, int out_size) {
    const float* x     = (const float*)d_in[0];  // [N, 64]
    const float* pos   = (const float*)d_in[1];  // [N, 3]
    const int*   ei    = (const int*)d_in[2];    // [2, E]
    const float* W     = (const float*)d_in[3];  // [64, 64]
    const float* b     = (const float*)d_in[4];  // [64]
    const float* gamma = (const float*)d_in[5];  // [64]
    const float* beta  = (const float*)d_in[6];  // [64]
    float* out = (float*)d_out;                  // [8000, 67]

    zero_kernel<<<512, 256>>>();
    gemm_kernel<<<NN / 64, 256>>>(x, W, b);
    stats_kernel<<<2048, 256>>>();
    scale_kernel<<<1, 64>>>(gamma, beta);
    hist_kernel<<<EE / 256, 256>>>(ei);
    offset_kernel<<<NN / 256, 256>>>();
    scatter_kernel<<<EE / 256, 256>>>(ei);
    gather_kernel<<<NN / 8, 256>>>(pos);
    out_kernel<<<(NVOX * 67 + 255) / 256, 256>>>(out);
}

// round 3
// speedup vs baseline: 2.3406x; 1.0146x over previous
#include <cuda_runtime.h>
#include <stdint.h>

// Problem constants
#define NN 262144
#define EE (NN * 16)
#define CC 64
#define NVOXD 20
#define NVOX 8000
#define BN_EPS 1e-5f
#define GRID_INV 2.0f   // 1/0.5
#define FULLMASK 0xFFFFFFFFu

// -------- scratch --------
__device__ float g_h[NN * CC];            // raw h = x@W+b (BN applied on the fly later)
__device__ float g_colsum[CC];
__device__ float g_colsq[CC];
__device__ float g_xsum[NVOX * CC];
__device__ float g_psum[NVOX * 3];
__device__ float g_cnt[NVOX];
__device__ int   g_cnt_i[NN];             // in-degree per node
__device__ int   g_off[NN];               // CSR offsets
__device__ int   g_cur[NN];               // scatter cursors
__device__ int   g_adj[EE];               // CSR adjacency (source rows per dest)
__device__ int   g_total;                 // global offset counter

// -------- 1: GEMM h = x @ W + b  (64 rows/block, 256 thr, f32x2 FFMA) --------
// Also zeroes per-call scratch that downstream kernels need (cnt_i, colsum, total).
__global__ __launch_bounds__(256) void gemm_kernel(const float* __restrict__ x,
                                                   const float* __restrict__ W,
                                                   const float* __restrict__ b) {
    __shared__ float Ws[64 * 64];      // row stride 64 floats
    __shared__ float xs[64][65];       // odd stride: conflict-free across rows
    int tid = threadIdx.x;
    int row0 = blockIdx.x * 64;

    // per-call zeroing folded into this (first) kernel
    if (tid < 64) g_cnt_i[row0 + tid] = 0;
    if (blockIdx.x == 0) {
        if (tid < 64) { g_colsum[tid] = 0.f; g_colsq[tid] = 0.f; }
        if (tid == 0) g_total = 0;
    }

#pragma unroll
    for (int i = tid; i < 4096; i += 256) Ws[i] = W[i];
#pragma unroll
    for (int i = tid; i < 4096; i += 256) xs[i >> 6][i & 63] = x[row0 * 64 + i];
    __syncthreads();

    int r = tid >> 2;
    int q = tid & 3;

    unsigned long long acc[8];
#pragma unroll
    for (int j = 0; j < 8; j++) {
        int p = q + 4 * j;
        unsigned int lo = __float_as_uint(b[2 * p]);
        unsigned int hi = __float_as_uint(b[2 * p + 1]);
        acc[j] = (unsigned long long)lo | ((unsigned long long)hi << 32);
    }

#pragma unroll 4
    for (int k = 0; k < 64; k++) {
        float xv = xs[r][k];
        unsigned int xu = __float_as_uint(xv);
        unsigned long long xvv;
        asm("mov.b64 %0, {%1, %1};" : "=l"(xvv) : "r"(xu));
        const unsigned long long* wrow =
            reinterpret_cast<const unsigned long long*>(&Ws[k * 64]);
#pragma unroll
        for (int j = 0; j < 8; j++) {
            unsigned long long w = wrow[q + 4 * j];
            asm("fma.rn.f32x2 %0, %1, %2, %0;" : "+l"(acc[j]) : "l"(w), "l"(xvv));
        }
    }

    unsigned long long* dst =
        reinterpret_cast<unsigned long long*>(&g_h[(long long)(row0 + r) * 64]);
#pragma unroll
    for (int j = 0; j < 8; j++) dst[q + 4 * j] = acc[j];
}

// -------- 2: fused column stats + in-degree histogram + accumulator zeroing --------
__global__ __launch_bounds__(256) void stats_hist_kernel(const int* __restrict__ ei) {
    int gid = blockIdx.x * blockDim.x + threadIdx.x;
    int gs = gridDim.x * blockDim.x;   // 524288, multiple of 64

    // zero voxel accumulators (needed before gather, which is 3 launches later)
    for (int j = gid; j < NVOX * CC; j += gs) g_xsum[j] = 0.f;
    for (int j = gid; j < NVOX * 3; j += gs)  g_psum[j] = 0.f;
    for (int j = gid; j < NVOX; j += gs)      g_cnt[j]  = 0.f;

    // in-degree histogram (atomic pipe; overlaps streaming reads below)
    for (int e = gid; e < EE; e += gs) atomicAdd(&g_cnt_i[ei[EE + e]], 1);

    // column stats: stride multiple of 64 -> fixed column per thread
    float s = 0.f, sq = 0.f;
    for (int i = gid; i < NN * CC; i += gs) {
        float v = g_h[i];
        s += v; sq += v * v;
    }
    __shared__ float ss[256], ssq[256];
    ss[threadIdx.x] = s; ssq[threadIdx.x] = sq;
    __syncthreads();
    if (threadIdx.x < 64) {
        float a  = ss[threadIdx.x] + ss[threadIdx.x + 64] + ss[threadIdx.x + 128] + ss[threadIdx.x + 192];
        float aq = ssq[threadIdx.x] + ssq[threadIdx.x + 64] + ssq[threadIdx.x + 128] + ssq[threadIdx.x + 192];
        atomicAdd(&g_colsum[threadIdx.x], a);
        atomicAdd(&g_colsq[threadIdx.x], aq);
    }
}

// -------- 3: offsets via warp-aggregated atomic (order-free CSR grouping) --------
__global__ __launch_bounds__(256) void offset_kernel() {
    int i = blockIdx.x * blockDim.x + threadIdx.x;
    int lane = threadIdx.x & 31;
    int c = g_cnt_i[i];
    int s = c;
#pragma unroll
    for (int d = 1; d < 32; d <<= 1) {
        int t = __shfl_up_sync(FULLMASK, s, d);
        if (lane >= d) s += t;
    }
    int total = __shfl_sync(FULLMASK, s, 31);
    int base = 0;
    if (lane == 31) base = atomicAdd(&g_total, total);
    base = __shfl_sync(FULLMASK, base, 31);
    int off = base + s - c;   // exclusive prefix within warp
    g_off[i] = off;
    g_cur[i] = off;
}

// -------- 4: scatter edge sources into CSR --------
__global__ __launch_bounds__(256) void scatter_kernel(const int* __restrict__ ei) {
    int e = blockIdx.x * blockDim.x + threadIdx.x;
    if (e >= EE) return;
    int row = ei[e];
    int col = ei[EE + e];
    int p = atomicAdd(&g_cur[col], 1);
    g_adj[p] = row;
}

// -------- 5: fused gather-max (BN+ReLU on the fly, inline scale) + voxel scatter --------
// Half-warp (16 lanes) per node; lane handles 4 channels (float4 = full 256B row/half-warp).
__global__ __launch_bounds__(256) void gather_kernel(const float* __restrict__ pos,
                                                     const float* __restrict__ gamma,
                                                     const float* __restrict__ beta) {
    int node = (blockIdx.x * blockDim.x + threadIdx.x) >> 4;
    int l = threadIdx.x & 15;                    // lane within half-warp
    int lanebase = threadIdx.x & 16;             // 0 or 16: half's base lane in warp
    unsigned int hmask = 0xFFFFu << lanebase;    // this half's shfl mask
    if (node >= NN) return;

    // inline BN scale/shift for channels 4l..4l+3
    float4 cs = *reinterpret_cast<const float4*>(&g_colsum[4 * l]);
    float4 cq = *reinterpret_cast<const float4*>(&g_colsq[4 * l]);
    float4 gm = *reinterpret_cast<const float4*>(&gamma[4 * l]);
    float4 bt = *reinterpret_cast<const float4*>(&beta[4 * l]);
    const float invn = 1.0f / NN;
    float m0 = cs.x * invn, m1 = cs.y * invn, m2 = cs.z * invn, m3 = cs.w * invn;
    float sc0 = gm.x * rsqrtf(cq.x * invn - m0 * m0 + BN_EPS);
    float sc1 = gm.y * rsqrtf(cq.y * invn - m1 * m1 + BN_EPS);
    float sc2 = gm.z * rsqrtf(cq.z * invn - m2 * m2 + BN_EPS);
    float sc3 = gm.w * rsqrtf(cq.w * invn - m3 * m3 + BN_EPS);
    float sh0 = bt.x - m0 * sc0, sh1 = bt.y - m1 * sc1;
    float sh2 = bt.z - m2 * sc2, sh3 = bt.w - m3 * sc3;

    const float4* h4 = reinterpret_cast<const float4*>(g_h);
    float4 v = __ldg(&h4[(long long)node * 16 + l]);
    // self (ReLU'd). Neighbors can skip ReLU: max(a>=0, y) == max(a, relu(y)).
    float a0 = fmaxf(fmaf(v.x, sc0, sh0), 0.f);
    float a1 = fmaxf(fmaf(v.y, sc1, sh1), 0.f);
    float a2 = fmaxf(fmaf(v.z, sc2, sh2), 0.f);
    float a3 = fmaxf(fmaf(v.w, sc3, sh3), 0.f);

    int off = g_off[node];
    int cnt = g_cnt_i[node];
    int nb = (cnt + 15) >> 4;
    for (int bj = 0; bj < nb; bj++) {
        int j = bj * 16 + l;
        // pad with self: self row is L1-hot, no extra L2 traffic
        int idx = (j < cnt) ? g_adj[off + j] : node;
#pragma unroll
        for (int t = 0; t < 16; t++) {
            int src = __shfl_sync(hmask, idx, lanebase + t);
            float4 u = __ldg(&h4[(long long)src * 16 + l]);
            a0 = fmaxf(a0, fmaf(u.x, sc0, sh0));
            a1 = fmaxf(a1, fmaf(u.y, sc1, sh1));
            a2 = fmaxf(a2, fmaf(u.z, sc2, sh2));
            a3 = fmaxf(a3, fmaf(u.w, sc3, sh3));
        }
    }

    // voxel id (computed by lane 0 of the half, broadcast)
    float px = 0.f, py = 0.f, pz = 0.f;
    int vox = 0;
    if (l == 0) {
        px = pos[node * 3 + 0];
        py = pos[node * 3 + 1];
        pz = pos[node * 3 + 2];
        int vx = min(max((int)floorf(px * GRID_INV), 0), NVOXD - 1);
        int vy = min(max((int)floorf(py * GRID_INV), 0), NVOXD - 1);
        int vz = min(max((int)floorf(pz * GRID_INV), 0), NVOXD - 1);
        vox = (vx * NVOXD + vy) * NVOXD + vz;
    }
    vox = __shfl_sync(hmask, vox, lanebase);

    float* xbase = &g_xsum[(long long)vox * 64 + 4 * l];
    asm volatile("red.global.add.v4.f32 [%0], {%1, %2, %3, %4};"
                 :: "l"(xbase), "f"(a0), "f"(a1), "f"(a2), "f"(a3) : "memory");
    if (l == 0) {
        atomicAdd(&g_cnt[vox], 1.0f);
        atomicAdd(&g_psum[vox * 3 + 0], px);
        atomicAdd(&g_psum[vox * 3 + 1], py);
        atomicAdd(&g_psum[vox * 3 + 2], pz);
    }
}

// -------- 6: finalize output [NVOX, 67] --------
__global__ void out_kernel(float* __restrict__ out) {
    int i = blockIdx.x * blockDim.x + threadIdx.x;
    if (i >= NVOX * 67) return;
    int v = i / 67;
    int c = i - v * 67;
    float denom = fmaxf(g_cnt[v], 1.0f);
    float val = (c < 64) ? g_xsum[v * 64 + c] : g_psum[v * 3 + (c - 64)];
    out[i] = val / denom;
}

extern "C" void kernel_launch(void* const* d_in, const int* in_sizes, int n_in,
                              void* d_out, int out_size) {
    const float* x     = (const float*)d_in[0];  // [N, 64]
    const float* pos   = (const float*)d_in[1];  // [N, 3]
    const int*   ei    = (const int*)d_in[2];    // [2, E]
    const float* W     = (const float*)d_in[3];  // [64, 64]
    const float* b     = (const float*)d_in[4];  // [64]
    const float* gamma = (const float*)d_in[5];  // [64]
    const float* beta  = (const float*)d_in[6];  // [64]
    float* out = (float*)d_out;                  // [8000, 67]

    gemm_kernel<<<NN / 64, 256>>>(x, W, b);
    stats_hist_kernel<<<2048, 256>>>(ei);
    offset_kernel<<<NN / 256, 256>>>();
    scatter_kernel<<<EE / 256, 256>>>(ei);
    gather_kernel<<<NN / 16, 256>>>(pos, gamma, beta);
    out_kernel<<<(NVOX * 67 + 255) / 256, 256>>>(out);
}

// round 4
// speedup vs baseline: 2.4842x; 1.0614x over previous
#include <cuda_runtime.h>
#include <stdint.h>

// Problem constants
#define NN 262144
#define EE (NN * 16)
#define CC 64
#define NVOXD 20
#define NVOX 8000
#define BN_EPS 1e-5f
#define GRID_INV 2.0f   // 1/0.5
#define FULLMASK 0xFFFFFFFFu

// -------- scratch --------
__device__ float g_h[NN * CC];            // raw h = x@W+b (BN applied on the fly later)
__device__ float g_colsum[CC];
__device__ float g_colsq[CC];
__device__ float g_xsum[NVOX * CC];
__device__ float g_psum[NVOX * 3];
__device__ float g_cnt[NVOX];
__device__ int   g_cnt_i[NN];             // in-degree per node
__device__ int   g_off[NN];               // CSR offsets
__device__ int   g_cur[NN];               // scatter cursors
__device__ int   g_adj[EE];               // CSR adjacency (source rows per dest)
__device__ int   g_total;                 // global offset counter

// ======================= STREAM A: gemm -> stats =======================

// -------- A1: GEMM h = x @ W + b  (64 rows/block, 256 thr, f32x2 FFMA) --------
__global__ __launch_bounds__(256) void gemm_kernel(const float* __restrict__ x,
                                                   const float* __restrict__ W,
                                                   const float* __restrict__ b) {
    __shared__ float Ws[64 * 64];      // row stride 64 floats
    __shared__ float xs[64][65];       // odd stride: conflict-free across rows
    int tid = threadIdx.x;
    int row0 = blockIdx.x * 64;

    if (blockIdx.x == 0 && tid < 64) { g_colsum[tid] = 0.f; g_colsq[tid] = 0.f; }

#pragma unroll
    for (int i = tid; i < 4096; i += 256) Ws[i] = W[i];
#pragma unroll
    for (int i = tid; i < 4096; i += 256) xs[i >> 6][i & 63] = x[row0 * 64 + i];
    __syncthreads();

    int r = tid >> 2;
    int q = tid & 3;

    unsigned long long acc[8];
#pragma unroll
    for (int j = 0; j < 8; j++) {
        int p = q + 4 * j;
        unsigned int lo = __float_as_uint(b[2 * p]);
        unsigned int hi = __float_as_uint(b[2 * p + 1]);
        acc[j] = (unsigned long long)lo | ((unsigned long long)hi << 32);
    }

#pragma unroll 4
    for (int k = 0; k < 64; k++) {
        float xv = xs[r][k];
        unsigned int xu = __float_as_uint(xv);
        unsigned long long xvv;
        asm("mov.b64 %0, {%1, %1};" : "=l"(xvv) : "r"(xu));
        const unsigned long long* wrow =
            reinterpret_cast<const unsigned long long*>(&Ws[k * 64]);
#pragma unroll
        for (int j = 0; j < 8; j++) {
            unsigned long long w = wrow[q + 4 * j];
            asm("fma.rn.f32x2 %0, %1, %2, %0;" : "+l"(acc[j]) : "l"(w), "l"(xvv));
        }
    }

    unsigned long long* dst =
        reinterpret_cast<unsigned long long*>(&g_h[(long long)(row0 + r) * 64]);
#pragma unroll
    for (int j = 0; j < 8; j++) dst[q + 4 * j] = acc[j];
}

// -------- A2: per-column sum / sumsq over raw h --------
__global__ __launch_bounds__(256) void stats_kernel() {
    float s = 0.f, sq = 0.f;
    int stride = gridDim.x * blockDim.x;      // multiple of 64 -> fixed column per thread
    for (int i = blockIdx.x * blockDim.x + threadIdx.x; i < NN * CC; i += stride) {
        float v = g_h[i];
        s += v; sq += v * v;
    }
    __shared__ float ss[256], ssq[256];
    ss[threadIdx.x] = s; ssq[threadIdx.x] = sq;
    __syncthreads();
    if (threadIdx.x < 64) {
        float a  = ss[threadIdx.x] + ss[threadIdx.x + 64] + ss[threadIdx.x + 128] + ss[threadIdx.x + 192];
        float aq = ssq[threadIdx.x] + ssq[threadIdx.x + 64] + ssq[threadIdx.x + 128] + ssq[threadIdx.x + 192];
        atomicAdd(&g_colsum[threadIdx.x], a);
        atomicAdd(&g_colsq[threadIdx.x], aq);
    }
}

// ================= STREAM B: zero -> hist -> offset -> scatter =================

// -------- B1: zero per-call accumulators used by the CSR chain + gather --------
__global__ __launch_bounds__(256) void zeroB_kernel() {
    int gid = blockIdx.x * blockDim.x + threadIdx.x;
    int gs = gridDim.x * blockDim.x;
    for (int j = gid; j < NN; j += gs)        g_cnt_i[j] = 0;
    for (int j = gid; j < NVOX * CC; j += gs) g_xsum[j] = 0.f;
    for (int j = gid; j < NVOX * 3; j += gs)  g_psum[j] = 0.f;
    for (int j = gid; j < NVOX; j += gs)      g_cnt[j]  = 0.f;
    if (gid == 0) g_total = 0;
}

// -------- B2: in-degree histogram --------
__global__ __launch_bounds__(256) void hist_kernel(const int* __restrict__ ei) {
    int e = blockIdx.x * blockDim.x + threadIdx.x;
    if (e < EE) atomicAdd(&g_cnt_i[ei[EE + e]], 1);
}

// -------- B3: offsets via warp-aggregated atomic (order-free CSR grouping) --------
__global__ __launch_bounds__(256) void offset_kernel() {
    int i = blockIdx.x * blockDim.x + threadIdx.x;
    int lane = threadIdx.x & 31;
    int c = g_cnt_i[i];
    int s = c;
#pragma unroll
    for (int d = 1; d < 32; d <<= 1) {
        int t = __shfl_up_sync(FULLMASK, s, d);
        if (lane >= d) s += t;
    }
    int total = __shfl_sync(FULLMASK, s, 31);
    int base = 0;
    if (lane == 31) base = atomicAdd(&g_total, total);
    base = __shfl_sync(FULLMASK, base, 31);
    int off = base + s - c;   // exclusive prefix within warp
    g_off[i] = off;
    g_cur[i] = off;
}

// -------- B4: scatter edge sources into CSR --------
__global__ __launch_bounds__(256) void scatter_kernel(const int* __restrict__ ei) {
    int e = blockIdx.x * blockDim.x + threadIdx.x;
    if (e >= EE) return;
    int row = ei[e];
    int col = ei[EE + e];
    int p = atomicAdd(&g_cur[col], 1);
    g_adj[p] = row;
}

// ======================= JOINED: gather -> out =======================

// -------- fused gather-max (BN+ReLU on the fly, inline scale) + voxel scatter --------
// Half-warp (16 lanes) per node; lane handles 4 channels (float4 = full 256B row/half-warp).
__global__ __launch_bounds__(256) void gather_kernel(const float* __restrict__ pos,
                                                     const float* __restrict__ gamma,
                                                     const float* __restrict__ beta) {
    int node = (blockIdx.x * blockDim.x + threadIdx.x) >> 4;
    int l = threadIdx.x & 15;                    // lane within half-warp
    int lanebase = threadIdx.x & 16;             // 0 or 16: half's base lane in warp
    unsigned int hmask = 0xFFFFu << lanebase;    // this half's shfl mask
    if (node >= NN) return;

    // inline BN scale/shift for channels 4l..4l+3
    float4 cs = *reinterpret_cast<const float4*>(&g_colsum[4 * l]);
    float4 cq = *reinterpret_cast<const float4*>(&g_colsq[4 * l]);
    float4 gm = *reinterpret_cast<const float4*>(&gamma[4 * l]);
    float4 bt = *reinterpret_cast<const float4*>(&beta[4 * l]);
    const float invn = 1.0f / NN;
    float m0 = cs.x * invn, m1 = cs.y * invn, m2 = cs.z * invn, m3 = cs.w * invn;
    float sc0 = gm.x * rsqrtf(cq.x * invn - m0 * m0 + BN_EPS);
    float sc1 = gm.y * rsqrtf(cq.y * invn - m1 * m1 + BN_EPS);
    float sc2 = gm.z * rsqrtf(cq.z * invn - m2 * m2 + BN_EPS);
    float sc3 = gm.w * rsqrtf(cq.w * invn - m3 * m3 + BN_EPS);
    float sh0 = bt.x - m0 * sc0, sh1 = bt.y - m1 * sc1;
    float sh2 = bt.z - m2 * sc2, sh3 = bt.w - m3 * sc3;

    const float4* h4 = reinterpret_cast<const float4*>(g_h);
    float4 v = __ldg(&h4[(long long)node * 16 + l]);
    // self (ReLU'd). Neighbors can skip ReLU: max(a>=0, y) == max(a, relu(y)).
    float a0 = fmaxf(fmaf(v.x, sc0, sh0), 0.f);
    float a1 = fmaxf(fmaf(v.y, sc1, sh1), 0.f);
    float a2 = fmaxf(fmaf(v.z, sc2, sh2), 0.f);
    float a3 = fmaxf(fmaf(v.w, sc3, sh3), 0.f);

    int off = g_off[node];
    int cnt = g_cnt_i[node];
    int nb = (cnt + 15) >> 4;
    for (int bj = 0; bj < nb; bj++) {
        int j = bj * 16 + l;
        // pad with self: self row is L1-hot, no extra L2 traffic
        int idx = (j < cnt) ? g_adj[off + j] : node;
#pragma unroll
        for (int t = 0; t < 16; t++) {
            int src = __shfl_sync(hmask, idx, lanebase + t);
            float4 u = __ldg(&h4[(long long)src * 16 + l]);
            a0 = fmaxf(a0, fmaf(u.x, sc0, sh0));
            a1 = fmaxf(a1, fmaf(u.y, sc1, sh1));
            a2 = fmaxf(a2, fmaf(u.z, sc2, sh2));
            a3 = fmaxf(a3, fmaf(u.w, sc3, sh3));
        }
    }

    // voxel id (computed by lane 0 of the half, broadcast)
    float px = 0.f, py = 0.f, pz = 0.f;
    int vox = 0;
    if (l == 0) {
        px = pos[node * 3 + 0];
        py = pos[node * 3 + 1];
        pz = pos[node * 3 + 2];
        int vx = min(max((int)floorf(px * GRID_INV), 0), NVOXD - 1);
        int vy = min(max((int)floorf(py * GRID_INV), 0), NVOXD - 1);
        int vz = min(max((int)floorf(pz * GRID_INV), 0), NVOXD - 1);
        vox = (vx * NVOXD + vy) * NVOXD + vz;
    }
    vox = __shfl_sync(hmask, vox, lanebase);

    float* xbase = &g_xsum[(long long)vox * 64 + 4 * l];
    asm volatile("red.global.add.v4.f32 [%0], {%1, %2, %3, %4};"
                 :: "l"(xbase), "f"(a0), "f"(a1), "f"(a2), "f"(a3) : "memory");
    if (l == 0) {
        atomicAdd(&g_cnt[vox], 1.0f);
        atomicAdd(&g_psum[vox * 3 + 0], px);
        atomicAdd(&g_psum[vox * 3 + 1], py);
        atomicAdd(&g_psum[vox * 3 + 2], pz);
    }
}

// -------- finalize output [NVOX, 67] --------
__global__ void out_kernel(float* __restrict__ out) {
    int i = blockIdx.x * blockDim.x + threadIdx.x;
    if (i >= NVOX * 67) return;
    int v = i / 67;
    int c = i - v * 67;
    float denom = fmaxf(g_cnt[v], 1.0f);
    float val = (c < 64) ? g_xsum[v * 64 + c] : g_psum[v * 3 + (c - 64)];
    out[i] = val / denom;
}

extern "C" void kernel_launch(void* const* d_in, const int* in_sizes, int n_in,
                              void* d_out, int out_size) {
    const float* x     = (const float*)d_in[0];  // [N, 64]
    const float* pos   = (const float*)d_in[1];  // [N, 3]
    const int*   ei    = (const int*)d_in[2];    // [2, E]
    const float* W     = (const float*)d_in[3];  // [64, 64]
    const float* b     = (const float*)d_in[4];  // [64]
    const float* gamma = (const float*)d_in[5];  // [64]
    const float* beta  = (const float*)d_in[6];  // [64]
    float* out = (float*)d_out;                  // [8000, 67]

    // one-time host resources (created on the first, non-captured, correctness call)
    static cudaStream_t sB = nullptr;
    static cudaEvent_t evFork = nullptr, evJoin = nullptr;
    if (sB == nullptr) {
        cudaStreamCreateWithFlags(&sB, cudaStreamNonBlocking);
        cudaEventCreateWithFlags(&evFork, cudaEventDisableTiming);
        cudaEventCreateWithFlags(&evJoin, cudaEventDisableTiming);
    }

    // fork: CSR build (stream B) runs concurrently with GEMM+stats (stream 0)
    cudaEventRecord(evFork, 0);
    cudaStreamWaitEvent(sB, evFork, 0);

    // Stream B: CSR build chain (independent of h)
    zeroB_kernel<<<512, 256, 0, sB>>>();
    hist_kernel<<<EE / 256, 256, 0, sB>>>(ei);
    offset_kernel<<<NN / 256, 256, 0, sB>>>();
    scatter_kernel<<<EE / 256, 256, 0, sB>>>(ei);
    cudaEventRecord(evJoin, sB);

    // Stream 0: GEMM -> stats
    gemm_kernel<<<NN / 64, 256>>>(x, W, b);
    stats_kernel<<<2048, 256>>>();

    // join, then gather + out on stream 0
    cudaStreamWaitEvent(0, evJoin, 0);
    gather_kernel<<<NN / 16, 256>>>(pos, gamma, beta);
    out_kernel<<<(NVOX * 67 + 255) / 256, 256>>>(out);
}

// round 5
// speedup vs baseline: 3.0739x; 1.2374x over previous
#include <cuda_runtime.h>
#include <stdint.h>

// Problem constants
#define NN 262144
#define EE (NN * 16)
#define CC 64
#define NVOXD 20
#define NVOX 8000
#define BN_EPS 1e-5f
#define GRID_INV 2.0f   // 1/0.5
#define FULLMASK 0xFFFFFFFFu

typedef unsigned long long ull;

// -------- scratch --------
__device__ float g_h[NN * CC];            // raw h = x@W+b (BN applied on the fly later)
__device__ float g_colsum[CC];            // zeroed by out_kernel tail (zero at load for call #1)
__device__ float g_colsq[CC];
__device__ float g_xsum[NVOX * CC];
__device__ float g_psum[NVOX * 3];
__device__ float g_cnt[NVOX];
__device__ int   g_cnt_i[NN];             // in-degree per node
__device__ int   g_off[NN];               // CSR offsets
__device__ int   g_cur[NN];               // scatter cursors
__device__ int   g_adj[EE];               // CSR adjacency (source rows per dest)
__device__ int   g_total;                 // global offset counter

// ======================= STREAM A: fused gemm + stats =======================
// 256 rows/block, 256 threads. Thread (r=tid>>2, q=tid&3) computes rows
// {r, r+64, r+128, r+192} x 16 cols (8 f32x2 pairs, cols 2(q+4j), 2(q+4j)+1).
// Per k: 4 LDS.32 (x) + 8 LDS.64 (W, broadcast) + 32 FFMA2.
// Epilogue reduces accumulators into per-column sum/sumsq (saves re-reading g_h).
#define GS_XS_STRIDE 66
#define GS_SMEM_FLOATS (256 * GS_XS_STRIDE + 64 * 64)
#define GS_SMEM_BYTES (GS_SMEM_FLOATS * 4)

__global__ __launch_bounds__(256) void gemm_stats_kernel(const float* __restrict__ x,
                                                         const float* __restrict__ W,
                                                         const float* __restrict__ b) {
    extern __shared__ float sm[];
    float* xs = sm;                                   // [256][66]
    float* Wsf = sm + 256 * GS_XS_STRIDE;             // [64][64]
    ull*   Wsu = reinterpret_cast<ull*>(Wsf);
    int tid = threadIdx.x;
    int row0 = blockIdx.x * 256;

#pragma unroll
    for (int i = tid; i < 4096; i += 256) Wsf[i] = W[i];
#pragma unroll 8
    for (int i = tid; i < 16384; i += 256) {
        int rr = i >> 6, cc = i & 63;
        xs[rr * GS_XS_STRIDE + cc] = x[(long long)row0 * 64 + i];
    }
    __syncthreads();

    int r = tid >> 2;
    int q = tid & 3;

    ull acc[4][8];
#pragma unroll
    for (int j = 0; j < 8; j++) {
        int p = q + 4 * j;
        ull base = (ull)__float_as_uint(b[2 * p]) | ((ull)__float_as_uint(b[2 * p + 1]) << 32);
#pragma unroll
        for (int s = 0; s < 4; s++) acc[s][j] = base;
    }

#pragma unroll 2
    for (int k = 0; k < 64; k++) {
        ull xv[4];
#pragma unroll
        for (int s = 0; s < 4; s++) {
            unsigned int u = __float_as_uint(xs[(r + 64 * s) * GS_XS_STRIDE + k]);
            asm("mov.b64 %0, {%1, %1};" : "=l"(xv[s]) : "r"(u));
        }
        const ull* wrow = Wsu + k * 32;
#pragma unroll
        for (int j = 0; j < 8; j++) {
            ull w = wrow[q + 4 * j];
#pragma unroll
            for (int s = 0; s < 4; s++)
                asm("fma.rn.f32x2 %0, %1, %2, %0;" : "+l"(acc[s][j]) : "l"(w), "l"(xv[s]));
        }
    }

    ull* hd = reinterpret_cast<ull*>(g_h);
#pragma unroll
    for (int s = 0; s < 4; s++)
#pragma unroll
        for (int j = 0; j < 8; j++)
            hd[(long long)(row0 + r + 64 * s) * 32 + q + 4 * j] = acc[s][j];

    // ---- stats epilogue: per-column sum / sumsq from live accumulators ----
    float sl[8], sh[8], ql[8], qh[8];
#pragma unroll
    for (int j = 0; j < 8; j++) {
        sl[j] = 0.f; sh[j] = 0.f; ql[j] = 0.f; qh[j] = 0.f;
#pragma unroll
        for (int s = 0; s < 4; s++) {
            float lo = __uint_as_float((unsigned int)acc[s][j]);
            float hi = __uint_as_float((unsigned int)(acc[s][j] >> 32));
            sl[j] += lo; sh[j] += hi;
            ql[j] += lo * lo; qh[j] += hi * hi;
        }
    }
    // reduce across the 8 r-threads sharing q within each warp (lanes xor 4,8,16)
#pragma unroll
    for (int j = 0; j < 8; j++) {
#pragma unroll
        for (int d = 4; d < 32; d <<= 1) {
            sl[j] += __shfl_xor_sync(FULLMASK, sl[j], d);
            sh[j] += __shfl_xor_sync(FULLMASK, sh[j], d);
            ql[j] += __shfl_xor_sync(FULLMASK, ql[j], d);
            qh[j] += __shfl_xor_sync(FULLMASK, qh[j], d);
        }
    }
    __syncthreads();                 // xs reads done; reuse as reduction buffer
    float* ssum = xs;                // [64]
    float* ssq  = xs + 64;           // [64]
    if (tid < 128) xs[tid] = 0.f;
    __syncthreads();
    if ((threadIdx.x & 31) < 4) {    // lanes 0..3 hold warp-reduced values
#pragma unroll
        for (int j = 0; j < 8; j++) {
            int c = 2 * (q + 4 * j);
            atomicAdd(&ssum[c], sl[j]);  atomicAdd(&ssum[c + 1], sh[j]);
            atomicAdd(&ssq[c],  ql[j]);  atomicAdd(&ssq[c + 1],  qh[j]);
        }
    }
    __syncthreads();
    if (tid < 64) {
        atomicAdd(&g_colsum[tid], ssum[tid]);
        atomicAdd(&g_colsq[tid],  ssq[tid]);
    }
}

// ================= STREAM B: zero -> hist -> offset -> scatter =================

__global__ __launch_bounds__(256) void zeroB_kernel() {
    int gid = blockIdx.x * blockDim.x + threadIdx.x;
    int gs = gridDim.x * blockDim.x;
    for (int j = gid; j < NN; j += gs)        g_cnt_i[j] = 0;
    for (int j = gid; j < NVOX * CC; j += gs) g_xsum[j] = 0.f;
    for (int j = gid; j < NVOX * 3; j += gs)  g_psum[j] = 0.f;
    for (int j = gid; j < NVOX; j += gs)      g_cnt[j]  = 0.f;
    if (gid == 0) g_total = 0;
}

__global__ __launch_bounds__(256) void hist_kernel(const int* __restrict__ ei) {
    int e = blockIdx.x * blockDim.x + threadIdx.x;
    if (e < EE) atomicAdd(&g_cnt_i[ei[EE + e]], 1);
}

__global__ __launch_bounds__(256) void offset_kernel() {
    int i = blockIdx.x * blockDim.x + threadIdx.x;
    int lane = threadIdx.x & 31;
    int c = g_cnt_i[i];
    int s = c;
#pragma unroll
    for (int d = 1; d < 32; d <<= 1) {
        int t = __shfl_up_sync(FULLMASK, s, d);
        if (lane >= d) s += t;
    }
    int total = __shfl_sync(FULLMASK, s, 31);
    int base = 0;
    if (lane == 31) base = atomicAdd(&g_total, total);
    base = __shfl_sync(FULLMASK, base, 31);
    int off = base + s - c;   // exclusive prefix within warp
    g_off[i] = off;
    g_cur[i] = off;
}

__global__ __launch_bounds__(256) void scatter_kernel(const int* __restrict__ ei) {
    int e = blockIdx.x * blockDim.x + threadIdx.x;
    if (e >= EE) return;
    int row = ei[e];
    int col = ei[EE + e];
    int p = atomicAdd(&g_cur[col], 1);
    g_adj[p] = row;
}

// ======================= JOINED: gather -> out =======================
// Half-warp (16 lanes) per node; lane handles 4 channels (float4).
__global__ __launch_bounds__(256) void gather_kernel(const float* __restrict__ pos,
                                                     const float* __restrict__ gamma,
                                                     const float* __restrict__ beta) {
    int node = (blockIdx.x * blockDim.x + threadIdx.x) >> 4;
    int l = threadIdx.x & 15;                    // lane within half-warp
    int lanebase = threadIdx.x & 16;             // 0 or 16
    unsigned int hmask = 0xFFFFu << lanebase;

    // --- issue long-latency loads first (overlap with BN constant math) ---
    int off = g_off[node];
    int cnt = g_cnt_i[node];
    int idx = (l < cnt) ? g_adj[off + l] : node; // first batch indices
    float px = 0.f, py = 0.f, pz = 0.f;
    int vox = 0;
    if (l == 0) {
        px = pos[node * 3 + 0];
        py = pos[node * 3 + 1];
        pz = pos[node * 3 + 2];
    }
    const float4* h4 = reinterpret_cast<const float4*>(g_h);
    float4 v = __ldg(&h4[(long long)node * 16 + l]);   // self row

    // inline BN scale/shift for channels 4l..4l+3
    float4 cs = *reinterpret_cast<const float4*>(&g_colsum[4 * l]);
    float4 cq = *reinterpret_cast<const float4*>(&g_colsq[4 * l]);
    float4 gm = *reinterpret_cast<const float4*>(&gamma[4 * l]);
    float4 bt = *reinterpret_cast<const float4*>(&beta[4 * l]);
    const float invn = 1.0f / NN;
    float m0 = cs.x * invn, m1 = cs.y * invn, m2 = cs.z * invn, m3 = cs.w * invn;
    float sc0 = gm.x * rsqrtf(cq.x * invn - m0 * m0 + BN_EPS);
    float sc1 = gm.y * rsqrtf(cq.y * invn - m1 * m1 + BN_EPS);
    float sc2 = gm.z * rsqrtf(cq.z * invn - m2 * m2 + BN_EPS);
    float sc3 = gm.w * rsqrtf(cq.w * invn - m3 * m3 + BN_EPS);
    float sh0 = bt.x - m0 * sc0, sh1 = bt.y - m1 * sc1;
    float sh2 = bt.z - m2 * sc2, sh3 = bt.w - m3 * sc3;

    if (l == 0) {
        int vx = min(max((int)floorf(px * GRID_INV), 0), NVOXD - 1);
        int vy = min(max((int)floorf(py * GRID_INV), 0), NVOXD - 1);
        int vz = min(max((int)floorf(pz * GRID_INV), 0), NVOXD - 1);
        vox = (vx * NVOXD + vy) * NVOXD + vz;
    }
    vox = __shfl_sync(hmask, vox, lanebase);

    // self (ReLU'd). Neighbors can skip ReLU: max(a>=0, y) == max(a, relu(y)).
    float a0 = fmaxf(fmaf(v.x, sc0, sh0), 0.f);
    float a1 = fmaxf(fmaf(v.y, sc1, sh1), 0.f);
    float a2 = fmaxf(fmaf(v.z, sc2, sh2), 0.f);
    float a3 = fmaxf(fmaf(v.w, sc3, sh3), 0.f);

    int nb = (cnt + 15) >> 4;
    for (int bj = 0; bj < nb; bj++) {
        if (bj) {
            int j = bj * 16 + l;
            idx = (j < cnt) ? g_adj[off + j] : node;   // pad with self (L1-hot)
        }
#pragma unroll
        for (int t = 0; t < 16; t++) {
            int src = __shfl_sync(hmask, idx, lanebase + t);
            float4 u = __ldg(&h4[(long long)src * 16 + l]);
            a0 = fmaxf(a0, fmaf(u.x, sc0, sh0));
            a1 = fmaxf(a1, fmaf(u.y, sc1, sh1));
            a2 = fmaxf(a2, fmaf(u.z, sc2, sh2));
            a3 = fmaxf(a3, fmaf(u.w, sc3, sh3));
        }
    }

    float* xbase = &g_xsum[(long long)vox * 64 + 4 * l];
    asm volatile("red.global.add.v4.f32 [%0], {%1, %2, %3, %4};"
                 :: "l"(xbase), "f"(a0), "f"(a1), "f"(a2), "f"(a3) : "memory");
    if (l == 0) {
        atomicAdd(&g_cnt[vox], 1.0f);
        atomicAdd(&g_psum[vox * 3 + 0], px);
        atomicAdd(&g_psum[vox * 3 + 1], py);
        atomicAdd(&g_psum[vox * 3 + 2], pz);
    }
}

// -------- finalize output [NVOX, 67]; tail-zero colsum/colsq for next replay ----
__global__ void out_kernel(float* __restrict__ out) {
    int i = blockIdx.x * blockDim.x + threadIdx.x;
    if (i < 64) { g_colsum[i] = 0.f; g_colsq[i] = 0.f; }   // runs after gather
    if (i >= NVOX * 67) return;
    int v = i / 67;
    int c = i - v * 67;
    float denom = fmaxf(g_cnt[v], 1.0f);
    float val = (c < 64) ? g_xsum[v * 64 + c] : g_psum[v * 3 + (c - 64)];
    out[i] = val / denom;
}

extern "C" void kernel_launch(void* const* d_in, const int* in_sizes, int n_in,
                              void* d_out, int out_size) {
    const float* x     = (const float*)d_in[0];  // [N, 64]
    const float* pos   = (const float*)d_in[1];  // [N, 3]
    const int*   ei    = (const int*)d_in[2];    // [2, E]
    const float* W     = (const float*)d_in[3];  // [64, 64]
    const float* b     = (const float*)d_in[4];  // [64]
    const float* gamma = (const float*)d_in[5];  // [64]
    const float* beta  = (const float*)d_in[6];  // [64]
    float* out = (float*)d_out;                  // [8000, 67]

    static cudaStream_t sB = nullptr;
    static cudaEvent_t evFork = nullptr, evJoin = nullptr;
    if (sB == nullptr) {
        cudaStreamCreateWithFlags(&sB, cudaStreamNonBlocking);
        cudaEventCreateWithFlags(&evFork, cudaEventDisableTiming);
        cudaEventCreateWithFlags(&evJoin, cudaEventDisableTiming);
        cudaFuncSetAttribute(gemm_stats_kernel,
                             cudaFuncAttributeMaxDynamicSharedMemorySize, GS_SMEM_BYTES);
    }

    // fork: CSR build (stream B) concurrent with fused GEMM+stats (stream 0)
    cudaEventRecord(evFork, 0);
    cudaStreamWaitEvent(sB, evFork, 0);

    // Submission order chosen so the 4th kernel launch (ncu capture slot) is the GEMM.
    zeroB_kernel<<<512, 256, 0, sB>>>();                       // 1
    hist_kernel<<<EE / 256, 256, 0, sB>>>(ei);                 // 2
    offset_kernel<<<NN / 256, 256, 0, sB>>>();                 // 3
    gemm_stats_kernel<<<NN / 256, 256, GS_SMEM_BYTES>>>(x, W, b); // 4 (stream 0)
    scatter_kernel<<<EE / 256, 256, 0, sB>>>(ei);              // 5
    cudaEventRecord(evJoin, sB);

    cudaStreamWaitEvent(0, evJoin, 0);
    gather_kernel<<<NN / 16, 256>>>(pos, gamma, beta);         // 6
    out_kernel<<<(NVOX * 67 + 255) / 256, 256>>>(out);         // 7
}

// round 6
// speedup vs baseline: 3.7085x; 1.2064x over previous
#include <cuda_runtime.h>
#include <cuda_fp16.h>
#include <stdint.h>

// Problem constants
#define NN 262144
#define EE (NN * 16)
#define CC 64
#define NVOXD 20
#define NVOX 8000
#define BN_EPS 1e-5f
#define GRID_INV 2.0f   // 1/0.5
#define FULLMASK 0xFFFFFFFFu

typedef unsigned long long ull;

// -------- scratch --------
__device__ __half g_hh[NN * CC];          // h = x@W+b in fp16 (BN applied later on the fly)
__device__ float g_colsum[CC];
__device__ float g_colsq[CC];
__device__ float g_scale[CC];
__device__ float g_shift[CC];
__device__ float g_xsum[NVOX * CC];
__device__ float g_psum[NVOX * 3];
__device__ float g_cnt[NVOX];
__device__ int   g_cnt_i[NN];             // in-degree per node (zeroed by prev call's out_kernel)
__device__ int   g_off[NN];               // CSR offsets
__device__ int   g_cur[NN];               // scatter cursors
__device__ int   g_adj[EE];               // CSR adjacency (source rows per dest)
__device__ int   g_total;                 // global offset counter

// ======================= STREAM A: fused gemm + stats (fp16 out) =======================
// 128 rows/block, 256 threads. q = tid&7 -> cols 8q..8q+7; r = tid>>3 -> rows r+32s, s=0..3.
// Per 4 k-steps/thread: 4 LDS.128 (x) + 8 LDS.128 (W) + 64 FFMA2.
#define GX_STRIDE 68   // 68 % 32 == 4 -> conflict-free LDS.128 across 4 rows
#define GS_SMEM_FLOATS (128 * GX_STRIDE + 64 * 64)
#define GS_SMEM_BYTES (GS_SMEM_FLOATS * 4)

__device__ __forceinline__ ull bcast2(float v) {
    ull r; unsigned u = __float_as_uint(v);
    asm("mov.b64 %0, {%1, %1};" : "=l"(r) : "r"(u));
    return r;
}
__device__ __forceinline__ ull pack2(unsigned lo, unsigned hi) {
    ull r; asm("mov.b64 %0, {%1, %2};" : "=l"(r) : "r"(lo), "r"(hi));
    return r;
}

__global__ __launch_bounds__(256) void gemm_stats_kernel(const float* __restrict__ x,
                                                         const float* __restrict__ W,
                                                         const float* __restrict__ b) {
    extern __shared__ float sm[];
    float* xs  = sm;                        // [128][GX_STRIDE]
    float* Wsf = sm + 128 * GX_STRIDE;      // [64][64]
    int tid = threadIdx.x;
    int row0 = blockIdx.x * 128;

#pragma unroll
    for (int i = tid; i < 1024; i += 256)
        reinterpret_cast<float4*>(Wsf)[i] = reinterpret_cast<const float4*>(W)[i];
#pragma unroll
    for (int i = tid; i < 2048; i += 256) {
        int row = i >> 4, c4 = i & 15;
        *reinterpret_cast<float4*>(&xs[row * GX_STRIDE + 4 * c4]) =
            reinterpret_cast<const float4*>(x + (long long)(row0 + row) * 64)[c4];
    }
    __syncthreads();

    int r = tid >> 3;          // 0..31
    int q = tid & 7;           // col group: cols 8q..8q+7

    ull acc[4][4];
#pragma unroll
    for (int d = 0; d < 4; d++) {
        ull base = pack2(__float_as_uint(b[8 * q + 2 * d]), __float_as_uint(b[8 * q + 2 * d + 1]));
#pragma unroll
        for (int s = 0; s < 4; s++) acc[s][d] = base;
    }

#pragma unroll 4
    for (int k4 = 0; k4 < 16; k4++) {
        float4 xv[4];
#pragma unroll
        for (int s = 0; s < 4; s++)
            xv[s] = *reinterpret_cast<float4*>(&xs[(r + 32 * s) * GX_STRIDE + 4 * k4]);
#pragma unroll
        for (int kk = 0; kk < 4; kk++) {
            const uint4* wr = reinterpret_cast<const uint4*>(&Wsf[(4 * k4 + kk) * 64 + 8 * q]);
            uint4 wa = wr[0], wb = wr[1];
            ull w0 = pack2(wa.x, wa.y), w1 = pack2(wa.z, wa.w);
            ull w2 = pack2(wb.x, wb.y), w3 = pack2(wb.z, wb.w);
#pragma unroll
            for (int s = 0; s < 4; s++) {
                float xe = (kk == 0) ? xv[s].x : (kk == 1) ? xv[s].y : (kk == 2) ? xv[s].z : xv[s].w;
                ull xb = bcast2(xe);
                asm("fma.rn.f32x2 %0, %1, %2, %0;" : "+l"(acc[s][0]) : "l"(w0), "l"(xb));
                asm("fma.rn.f32x2 %0, %1, %2, %0;" : "+l"(acc[s][1]) : "l"(w1), "l"(xb));
                asm("fma.rn.f32x2 %0, %1, %2, %0;" : "+l"(acc[s][2]) : "l"(w2), "l"(xb));
                asm("fma.rn.f32x2 %0, %1, %2, %0;" : "+l"(acc[s][3]) : "l"(w3), "l"(xb));
            }
        }
    }

    // store h as fp16 (8 cols = 16B per row-slice)
#pragma unroll
    for (int s = 0; s < 4; s++) {
        uint4 o;
        unsigned* op = &o.x;
#pragma unroll
        for (int d = 0; d < 4; d++) {
            float lo = __uint_as_float((unsigned)acc[s][d]);
            float hi = __uint_as_float((unsigned)(acc[s][d] >> 32));
            __half2 h2 = __floats2half2_rn(lo, hi);
            op[d] = *reinterpret_cast<unsigned*>(&h2);
        }
        *reinterpret_cast<uint4*>(&g_hh[(long long)(row0 + r + 32 * s) * 64 + 8 * q]) = o;
    }

    // ---- stats epilogue (fp32, from live accumulators) ----
    float su[8], sq[8];
#pragma unroll
    for (int d = 0; d < 4; d++) {
        float sl = 0.f, sh = 0.f, ql = 0.f, qh = 0.f;
#pragma unroll
        for (int s = 0; s < 4; s++) {
            float lo = __uint_as_float((unsigned)acc[s][d]);
            float hi = __uint_as_float((unsigned)(acc[s][d] >> 32));
            sl += lo; sh += hi; ql += lo * lo; qh += hi * hi;
        }
        su[2 * d] = sl; su[2 * d + 1] = sh;
        sq[2 * d] = ql; sq[2 * d + 1] = qh;
    }
#pragma unroll
    for (int e = 0; e < 8; e++) {
        su[e] += __shfl_xor_sync(FULLMASK, su[e], 8);
        su[e] += __shfl_xor_sync(FULLMASK, su[e], 16);
        sq[e] += __shfl_xor_sync(FULLMASK, sq[e], 8);
        sq[e] += __shfl_xor_sync(FULLMASK, sq[e], 16);
    }
    __syncthreads();                 // xs reads done; reuse as reduction buffer
    float* ssum = xs;                // [64]
    float* ssq  = xs + 64;           // [64]
    if (tid < 128) xs[tid] = 0.f;
    __syncthreads();
    if ((threadIdx.x & 31) < 8) {    // lanes 0..7 hold warp-reduced values, q = lane
#pragma unroll
        for (int e = 0; e < 8; e++) {
            atomicAdd(&ssum[8 * q + e], su[e]);
            atomicAdd(&ssq[8 * q + e],  sq[e]);
        }
    }
    __syncthreads();
    if (tid < 64) {
        atomicAdd(&g_colsum[tid], ssum[tid]);
        atomicAdd(&g_colsq[tid],  ssq[tid]);
    }
}

// -------- A2: fold BN into scale/shift (also resets colsum/colsq for next replay) --------
__global__ void scale_kernel(const float* __restrict__ gamma, const float* __restrict__ beta) {
    int c = threadIdx.x;
    if (c < CC) {
        float mean = g_colsum[c] * (1.0f / NN);
        float var = g_colsq[c] * (1.0f / NN) - mean * mean;
        float sc = gamma[c] * rsqrtf(var + BN_EPS);
        g_scale[c] = sc;
        g_shift[c] = beta[c] - mean * sc;
        g_colsum[c] = 0.f;
        g_colsq[c] = 0.f;
    }
}

// ================= STREAM B: hist(+zero acc) -> offset -> scatter =================

__global__ __launch_bounds__(256) void hist_kernel(const int* __restrict__ ei) {
    int gid = blockIdx.x * blockDim.x + threadIdx.x;   // grid covers EE exactly (4.19M)
    // zero voxel accumulators (single-shot; gid range >> sizes)
    if (gid < NVOX * CC) g_xsum[gid] = 0.f;
    if (gid < NVOX * 3)  g_psum[gid] = 0.f;
    if (gid < NVOX)      g_cnt[gid]  = 0.f;
    atomicAdd(&g_cnt_i[ei[EE + gid]], 1);
}

__global__ __launch_bounds__(256) void offset_kernel() {
    int i = blockIdx.x * blockDim.x + threadIdx.x;
    int lane = threadIdx.x & 31;
    int c = g_cnt_i[i];
    int s = c;
#pragma unroll
    for (int d = 1; d < 32; d <<= 1) {
        int t = __shfl_up_sync(FULLMASK, s, d);
        if (lane >= d) s += t;
    }
    int total = __shfl_sync(FULLMASK, s, 31);
    int base = 0;
    if (lane == 31) base = atomicAdd(&g_total, total);
    base = __shfl_sync(FULLMASK, base, 31);
    int off = base + s - c;   // exclusive prefix within warp
    g_off[i] = off;
    g_cur[i] = off;
}

__global__ __launch_bounds__(256) void scatter_kernel(const int* __restrict__ ei) {
    int e = blockIdx.x * blockDim.x + threadIdx.x;
    if (e >= EE) return;
    int row = ei[e];
    int col = ei[EE + e];
    int p = atomicAdd(&g_cur[col], 1);
    g_adj[p] = row;
}

// ======================= JOINED: gather (fp16 max/min) -> out =======================
// 8 lanes per node; lane handles 8 channels (uint4 = 8 halves = full 128B row per group).
// BN folded post-loop: relu(max(sc*max_h+sh, sc*min_h+sh)) is correct for any sign of sc.
__global__ __launch_bounds__(256) void gather_kernel(const float* __restrict__ pos) {
    int node = (blockIdx.x * blockDim.x + threadIdx.x) >> 3;
    int l = threadIdx.x & 7;                     // lane within 8-group
    int base8 = threadIdx.x & 24;                // group's base lane in warp
    unsigned int m8 = 0xFFu << base8;

    // long-latency loads first
    int off = g_off[node];
    int cnt = g_cnt_i[node];
    int idx = (l < cnt) ? g_adj[off + l] : node;  // first batch (pad with self)
    float px = 0.f, py = 0.f, pz = 0.f;
    if (l == 0) {
        px = pos[node * 3 + 0];
        py = pos[node * 3 + 1];
        pz = pos[node * 3 + 2];
    }
    const uint4* h8 = reinterpret_cast<const uint4*>(g_hh);
    uint4 self = __ldg(&h8[(long long)node * 8 + l]);

    __half2 mx0 = *reinterpret_cast<__half2*>(&self.x);
    __half2 mx1 = *reinterpret_cast<__half2*>(&self.y);
    __half2 mx2 = *reinterpret_cast<__half2*>(&self.z);
    __half2 mx3 = *reinterpret_cast<__half2*>(&self.w);
    __half2 mn0 = mx0, mn1 = mx1, mn2 = mx2, mn3 = mx3;

    int vox = 0;
    if (l == 0) {
        int vx = min(max((int)floorf(px * GRID_INV), 0), NVOXD - 1);
        int vy = min(max((int)floorf(py * GRID_INV), 0), NVOXD - 1);
        int vz = min(max((int)floorf(pz * GRID_INV), 0), NVOXD - 1);
        vox = (vx * NVOXD + vy) * NVOXD + vz;
    }
    vox = __shfl_sync(m8, vox, base8);

    int nb = (cnt + 7) >> 3;
    for (int bj = 0; bj < nb; bj++) {
        if (bj) {
            int j = bj * 8 + l;
            idx = (j < cnt) ? g_adj[off + j] : node;
        }
#pragma unroll
        for (int t = 0; t < 8; t++) {
            int src = __shfl_sync(m8, idx, base8 + t);
            uint4 u = __ldg(&h8[(long long)src * 8 + l]);
            __half2 u0 = *reinterpret_cast<__half2*>(&u.x);
            __half2 u1 = *reinterpret_cast<__half2*>(&u.y);
            __half2 u2 = *reinterpret_cast<__half2*>(&u.z);
            __half2 u3 = *reinterpret_cast<__half2*>(&u.w);
            mx0 = __hmax2(mx0, u0); mn0 = __hmin2(mn0, u0);
            mx1 = __hmax2(mx1, u1); mn1 = __hmin2(mn1, u1);
            mx2 = __hmax2(mx2, u2); mn2 = __hmin2(mn2, u2);
            mx3 = __hmax2(mx3, u3); mn3 = __hmin2(mn3, u3);
        }
    }

    // BN + ReLU finalize for channels 8l..8l+7
    float4 sca = *reinterpret_cast<const float4*>(&g_scale[8 * l]);
    float4 scb = *reinterpret_cast<const float4*>(&g_scale[8 * l + 4]);
    float4 sha = *reinterpret_cast<const float4*>(&g_shift[8 * l]);
    float4 shb = *reinterpret_cast<const float4*>(&g_shift[8 * l + 4]);

    float2 fx0 = __half22float2(mx0), fn0 = __half22float2(mn0);
    float2 fx1 = __half22float2(mx1), fn1 = __half22float2(mn1);
    float2 fx2 = __half22float2(mx2), fn2 = __half22float2(mn2);
    float2 fx3 = __half22float2(mx3), fn3 = __half22float2(mn3);

    float a0 = fmaxf(fmaxf(fmaf(fx0.x, sca.x, sha.x), fmaf(fn0.x, sca.x, sha.x)), 0.f);
    float a1 = fmaxf(fmaxf(fmaf(fx0.y, sca.y, sha.y), fmaf(fn0.y, sca.y, sha.y)), 0.f);
    float a2 = fmaxf(fmaxf(fmaf(fx1.x, sca.z, sha.z), fmaf(fn1.x, sca.z, sha.z)), 0.f);
    float a3 = fmaxf(fmaxf(fmaf(fx1.y, sca.w, sha.w), fmaf(fn1.y, sca.w, sha.w)), 0.f);
    float a4 = fmaxf(fmaxf(fmaf(fx2.x, scb.x, shb.x), fmaf(fn2.x, scb.x, shb.x)), 0.f);
    float a5 = fmaxf(fmaxf(fmaf(fx2.y, scb.y, shb.y), fmaf(fn2.y, scb.y, shb.y)), 0.f);
    float a6 = fmaxf(fmaxf(fmaf(fx3.x, scb.z, shb.z), fmaf(fn3.x, scb.z, shb.z)), 0.f);
    float a7 = fmaxf(fmaxf(fmaf(fx3.y, scb.w, shb.w), fmaf(fn3.y, scb.w, shb.w)), 0.f);

    float* xbase = &g_xsum[(long long)vox * 64 + 8 * l];
    asm volatile("red.global.add.v4.f32 [%0], {%1, %2, %3, %4};"
                 :: "l"(xbase), "f"(a0), "f"(a1), "f"(a2), "f"(a3) : "memory");
    asm volatile("red.global.add.v4.f32 [%0], {%1, %2, %3, %4};"
                 :: "l"(xbase + 4), "f"(a4), "f"(a5), "f"(a6), "f"(a7) : "memory");
    if (l == 0) {
        atomicAdd(&g_cnt[vox], 1.0f);
        atomicAdd(&g_psum[vox * 3 + 0], px);
        atomicAdd(&g_psum[vox * 3 + 1], py);
        atomicAdd(&g_psum[vox * 3 + 2], pz);
    }
}

// -------- finalize output [NVOX, 67]; tail-zero cnt_i/total for next replay --------
__global__ void out_kernel(float* __restrict__ out) {
    int i = blockIdx.x * blockDim.x + threadIdx.x;
    if (i < NN) g_cnt_i[i] = 0;        // grid is 536320 threads >= NN... (NN=262144)
    if (i == 0) g_total = 0;
    if (i >= NVOX * 67) return;
    int v = i / 67;
    int c = i - v * 67;
    float denom = fmaxf(g_cnt[v], 1.0f);
    float val = (c < 64) ? g_xsum[v * 64 + c] : g_psum[v * 3 + (c - 64)];
    out[i] = val / denom;
}

extern "C" void kernel_launch(void* const* d_in, const int* in_sizes, int n_in,
                              void* d_out, int out_size) {
    const float* x     = (const float*)d_in[0];  // [N, 64]
    const float* pos   = (const float*)d_in[1];  // [N, 3]
    const int*   ei    = (const int*)d_in[2];    // [2, E]
    const float* W     = (const float*)d_in[3];  // [64, 64]
    const float* b     = (const float*)d_in[4];  // [64]
    const float* gamma = (const float*)d_in[5];  // [64]
    const float* beta  = (const float*)d_in[6];  // [64]
    float* out = (float*)d_out;                  // [8000, 67]

    static cudaStream_t sB = nullptr;
    static cudaEvent_t evFork = nullptr, evJoin = nullptr;
    if (sB == nullptr) {
        cudaStreamCreateWithFlags(&sB, cudaStreamNonBlocking);
        cudaEventCreateWithFlags(&evFork, cudaEventDisableTiming);
        cudaEventCreateWithFlags(&evJoin, cudaEventDisableTiming);
        cudaFuncSetAttribute(gemm_stats_kernel,
                             cudaFuncAttributeMaxDynamicSharedMemorySize, GS_SMEM_BYTES);
    }

    // fork: CSR build (stream B) concurrent with GEMM+stats+scale (stream 0)
    cudaEventRecord(evFork, 0);
    cudaStreamWaitEvent(sB, evFork, 0);

    // Stream B (submitted 1-3): CSR build chain
    hist_kernel<<<EE / 256, 256, 0, sB>>>(ei);                     // 1
    offset_kernel<<<NN / 256, 256, 0, sB>>>();                     // 2
    scatter_kernel<<<EE / 256, 256, 0, sB>>>(ei);                  // 3
    cudaEventRecord(evJoin, sB);

    // Stream 0 (submitted 4-5): gemm (ncu capture slot #4) + BN fold
    gemm_stats_kernel<<<NN / 128, 256, GS_SMEM_BYTES>>>(x, W, b);  // 4
    scale_kernel<<<1, 64>>>(gamma, beta);                          // 5

    cudaStreamWaitEvent(0, evJoin, 0);
    gather_kernel<<<NN * 8 / 256, 256>>>(pos);                     // 6
    out_kernel<<<(NVOX * 67 + 255) / 256, 256>>>(out);             // 7
}

// round 7
// speedup vs baseline: 4.7856x; 1.2904x over previous
#include <cuda_runtime.h>
#include <cuda_fp16.h>
#include <stdint.h>

// Problem constants
#define NN 262144
#define EE (NN * 16)
#define CC 64
#define NVOXD 20
#define NVOX 8000
#define BN_EPS 1e-5f
#define GRID_INV 2.0f   // 1/0.5
#define FULLMASK 0xFFFFFFFFu
#define MAXDEG 64

typedef unsigned long long ull;

// -------- scratch --------
__device__ __half g_hh[NN * CC];          // h = x@W+b in fp16
__device__ float g_colsum[CC];
__device__ float g_colsq[CC];
__device__ float g_scale[CC];
__device__ float g_shift[CC];
__device__ float g_xsum[NVOX * CC];
__device__ float g_psum[NVOX * 3];
__device__ float g_cnt[NVOX];
__device__ int   g_cnt_i[NN];             // in-degree (zeroed by prev call's out_kernel / load-time)
__device__ int   g_adj[NN * MAXDEG];      // fixed-capacity per-node buckets

// ======================= STREAM A: fused gemm + stats (fp16 out) =======================
// 256 rows/block, 256 threads. q = tid&7 -> cols 8q..8q+7; r = tid>>3 -> rows r+32s, s=0..7.
// Per k4 per thread: 8 LDS.128 (x) + 8 LDS.128 (W) + 128 FFMA2 (1.5x less LDS/FFMA than R6).
#define GX_STRIDE 68   // stride%32==4 -> 4 r-groups land on disjoint bank quads
#define GS_SMEM_FLOATS (256 * GX_STRIDE + 64 * 64)
#define GS_SMEM_BYTES (GS_SMEM_FLOATS * 4)

__device__ __forceinline__ ull bcast2(float v) {
    ull r; unsigned u = __float_as_uint(v);
    asm("mov.b64 %0, {%1, %1};" : "=l"(r) : "r"(u));
    return r;
}
__device__ __forceinline__ ull pack2(unsigned lo, unsigned hi) {
    ull r; asm("mov.b64 %0, {%1, %2};" : "=l"(r) : "r"(lo), "r"(hi));
    return r;
}

__global__ __launch_bounds__(256) void gemm_stats_kernel(const float* __restrict__ x,
                                                         const float* __restrict__ W,
                                                         const float* __restrict__ b) {
    extern __shared__ float sm[];
    float* xs  = sm;                        // [256][GX_STRIDE]
    float* Wsf = sm + 256 * GX_STRIDE;      // [64][64]
    int tid = threadIdx.x;
    int row0 = blockIdx.x * 256;

#pragma unroll
    for (int i = tid; i < 1024; i += 256)
        reinterpret_cast<float4*>(Wsf)[i] = reinterpret_cast<const float4*>(W)[i];
#pragma unroll
    for (int i = tid; i < 4096; i += 256) {
        int row = i >> 4, c4 = i & 15;
        *reinterpret_cast<float4*>(&xs[row * GX_STRIDE + 4 * c4]) =
            reinterpret_cast<const float4*>(x + (long long)(row0 + row) * 64)[c4];
    }
    __syncthreads();

    int r = tid >> 3;          // 0..31
    int q = tid & 7;           // col group: cols 8q..8q+7

    ull acc[8][4];
#pragma unroll
    for (int d = 0; d < 4; d++) {
        ull base = pack2(__float_as_uint(b[8 * q + 2 * d]), __float_as_uint(b[8 * q + 2 * d + 1]));
#pragma unroll
        for (int s = 0; s < 8; s++) acc[s][d] = base;
    }

#pragma unroll 2
    for (int k4 = 0; k4 < 16; k4++) {
        float4 xv[8];
#pragma unroll
        for (int s = 0; s < 8; s++)
            xv[s] = *reinterpret_cast<float4*>(&xs[(r + 32 * s) * GX_STRIDE + 4 * k4]);
#pragma unroll
        for (int kk = 0; kk < 4; kk++) {
            const uint4* wr = reinterpret_cast<const uint4*>(&Wsf[(4 * k4 + kk) * 64 + 8 * q]);
            uint4 wa = wr[0], wb = wr[1];
            ull w0 = pack2(wa.x, wa.y), w1 = pack2(wa.z, wa.w);
            ull w2 = pack2(wb.x, wb.y), w3 = pack2(wb.z, wb.w);
#pragma unroll
            for (int s = 0; s < 8; s++) {
                float xe = (kk == 0) ? xv[s].x : (kk == 1) ? xv[s].y : (kk == 2) ? xv[s].z : xv[s].w;
                ull xb = bcast2(xe);
                asm("fma.rn.f32x2 %0, %1, %2, %0;" : "+l"(acc[s][0]) : "l"(w0), "l"(xb));
                asm("fma.rn.f32x2 %0, %1, %2, %0;" : "+l"(acc[s][1]) : "l"(w1), "l"(xb));
                asm("fma.rn.f32x2 %0, %1, %2, %0;" : "+l"(acc[s][2]) : "l"(w2), "l"(xb));
                asm("fma.rn.f32x2 %0, %1, %2, %0;" : "+l"(acc[s][3]) : "l"(w3), "l"(xb));
            }
        }
    }

    // store h as fp16 (8 cols = 16B per row-slice)
#pragma unroll
    for (int s = 0; s < 8; s++) {
        uint4 o;
        unsigned* op = &o.x;
#pragma unroll
        for (int d = 0; d < 4; d++) {
            float lo = __uint_as_float((unsigned)acc[s][d]);
            float hi = __uint_as_float((unsigned)(acc[s][d] >> 32));
            __half2 h2 = __floats2half2_rn(lo, hi);
            op[d] = *reinterpret_cast<unsigned*>(&h2);
        }
        *reinterpret_cast<uint4*>(&g_hh[(long long)(row0 + r + 32 * s) * 64 + 8 * q]) = o;
    }

    // ---- stats epilogue (fp32, from live accumulators) ----
    float su[8], sq[8];
#pragma unroll
    for (int d = 0; d < 4; d++) {
        float sl = 0.f, sh = 0.f, ql = 0.f, qh = 0.f;
#pragma unroll
        for (int s = 0; s < 8; s++) {
            float lo = __uint_as_float((unsigned)acc[s][d]);
            float hi = __uint_as_float((unsigned)(acc[s][d] >> 32));
            sl += lo; sh += hi; ql += lo * lo; qh += hi * hi;
        }
        su[2 * d] = sl; su[2 * d + 1] = sh;
        sq[2 * d] = ql; sq[2 * d + 1] = qh;
    }
#pragma unroll
    for (int e = 0; e < 8; e++) {
        su[e] += __shfl_xor_sync(FULLMASK, su[e], 8);
        su[e] += __shfl_xor_sync(FULLMASK, su[e], 16);
        sq[e] += __shfl_xor_sync(FULLMASK, sq[e], 8);
        sq[e] += __shfl_xor_sync(FULLMASK, sq[e], 16);
    }
    __syncthreads();                 // xs reads done; reuse as reduction buffer
    float* ssum = xs;                // [64]
    float* ssq  = xs + 64;           // [64]
    if (tid < 128) xs[tid] = 0.f;
    __syncthreads();
    if ((threadIdx.x & 31) < 8) {    // lanes 0..7 hold warp-reduced values, q = lane
#pragma unroll
        for (int e = 0; e < 8; e++) {
            atomicAdd(&ssum[8 * q + e], su[e]);
            atomicAdd(&ssq[8 * q + e],  sq[e]);
        }
    }
    __syncthreads();
    if (tid < 64) {
        atomicAdd(&g_colsum[tid], ssum[tid]);
        atomicAdd(&g_colsq[tid],  ssq[tid]);
    }
}

// -------- A2: fold BN into scale/shift (also resets colsum/colsq for next replay) --------
__global__ void scale_kernel(const float* __restrict__ gamma, const float* __restrict__ beta) {
    int c = threadIdx.x;
    if (c < CC) {
        float mean = g_colsum[c] * (1.0f / NN);
        float var = g_colsq[c] * (1.0f / NN) - mean * mean;
        float sc = gamma[c] * rsqrtf(var + BN_EPS);
        g_scale[c] = sc;
        g_shift[c] = beta[c] - mean * sc;
        g_colsum[c] = 0.f;
        g_colsq[c] = 0.f;
    }
}

// ================= STREAM B: single-kernel bucket CSR build (+zero acc) =================
__global__ __launch_bounds__(256) void scatter_kernel(const int* __restrict__ ei) {
    int e = blockIdx.x * blockDim.x + threadIdx.x;   // grid covers EE exactly
    // zero voxel accumulators (gid range >> sizes)
    if (e < NVOX * CC) g_xsum[e] = 0.f;
    if (e < NVOX * 3)  g_psum[e] = 0.f;
    if (e < NVOX)      g_cnt[e]  = 0.f;
    int row = ei[e];
    int col = ei[EE + e];
    int p = atomicAdd(&g_cnt_i[col], 1);
    if (p < MAXDEG) g_adj[col * MAXDEG + p] = row;
}

// ======================= JOINED: gather (fp16 max/min) -> out =======================
// 8 lanes per node; lane handles 8 channels (uint4 = 8 halves = full 128B row per group).
// Next-batch adjacency indices are prefetched while current batch's row loads fly.
__global__ __launch_bounds__(256) void gather_kernel(const float* __restrict__ pos) {
    int node = (blockIdx.x * blockDim.x + threadIdx.x) >> 3;
    int l = threadIdx.x & 7;                     // lane within 8-group
    int base8 = threadIdx.x & 24;                // group's base lane in warp
    unsigned int m8 = 0xFFu << base8;

    // long-latency loads first
    const int* bucket = &g_adj[(long long)node * MAXDEG];
    int cnt = min(g_cnt_i[node], MAXDEG);
    int idx_cur = (l < cnt) ? bucket[l] : node;  // first batch (pad with self)
    float px = 0.f, py = 0.f, pz = 0.f;
    if (l == 0) {
        px = pos[node * 3 + 0];
        py = pos[node * 3 + 1];
        pz = pos[node * 3 + 2];
    }
    const uint4* h8 = reinterpret_cast<const uint4*>(g_hh);
    uint4 self = __ldg(&h8[(long long)node * 8 + l]);

    __half2 mx0 = *reinterpret_cast<__half2*>(&self.x);
    __half2 mx1 = *reinterpret_cast<__half2*>(&self.y);
    __half2 mx2 = *reinterpret_cast<__half2*>(&self.z);
    __half2 mx3 = *reinterpret_cast<__half2*>(&self.w);
    __half2 mn0 = mx0, mn1 = mx1, mn2 = mx2, mn3 = mx3;

    int vox = 0;
    if (l == 0) {
        int vx = min(max((int)floorf(px * GRID_INV), 0), NVOXD - 1);
        int vy = min(max((int)floorf(py * GRID_INV), 0), NVOXD - 1);
        int vz = min(max((int)floorf(pz * GRID_INV), 0), NVOXD - 1);
        vox = (vx * NVOXD + vy) * NVOXD + vz;
    }
    vox = __shfl_sync(m8, vox, base8);

    int nb = (cnt + 7) >> 3;
    for (int bj = 0; bj < nb; bj++) {
        // prefetch next batch's indices (overlaps current batch's row loads)
        int jn = (bj + 1) * 8 + l;
        int idx_next = (jn < cnt) ? bucket[jn] : node;
#pragma unroll
        for (int t = 0; t < 8; t++) {
            int src = __shfl_sync(m8, idx_cur, base8 + t);
            uint4 u = __ldg(&h8[(long long)src * 8 + l]);
            __half2 u0 = *reinterpret_cast<__half2*>(&u.x);
            __half2 u1 = *reinterpret_cast<__half2*>(&u.y);
            __half2 u2 = *reinterpret_cast<__half2*>(&u.z);
            __half2 u3 = *reinterpret_cast<__half2*>(&u.w);
            mx0 = __hmax2(mx0, u0); mn0 = __hmin2(mn0, u0);
            mx1 = __hmax2(mx1, u1); mn1 = __hmin2(mn1, u1);
            mx2 = __hmax2(mx2, u2); mn2 = __hmin2(mn2, u2);
            mx3 = __hmax2(mx3, u3); mn3 = __hmin2(mn3, u3);
        }
        idx_cur = idx_next;
    }

    // BN + ReLU finalize: relu(max(sc*max_h+sh, sc*min_h+sh)) handles any sign of sc
    float4 sca = *reinterpret_cast<const float4*>(&g_scale[8 * l]);
    float4 scb = *reinterpret_cast<const float4*>(&g_scale[8 * l + 4]);
    float4 sha = *reinterpret_cast<const float4*>(&g_shift[8 * l]);
    float4 shb = *reinterpret_cast<const float4*>(&g_shift[8 * l + 4]);

    float2 fx0 = __half22float2(mx0), fn0 = __half22float2(mn0);
    float2 fx1 = __half22float2(mx1), fn1 = __half22float2(mn1);
    float2 fx2 = __half22float2(mx2), fn2 = __half22float2(mn2);
    float2 fx3 = __half22float2(mx3), fn3 = __half22float2(mn3);

    float a0 = fmaxf(fmaxf(fmaf(fx0.x, sca.x, sha.x), fmaf(fn0.x, sca.x, sha.x)), 0.f);
    float a1 = fmaxf(fmaxf(fmaf(fx0.y, sca.y, sha.y), fmaf(fn0.y, sca.y, sha.y)), 0.f);
    float a2 = fmaxf(fmaxf(fmaf(fx1.x, sca.z, sha.z), fmaf(fn1.x, sca.z, sha.z)), 0.f);
    float a3 = fmaxf(fmaxf(fmaf(fx1.y, sca.w, sha.w), fmaf(fn1.y, sca.w, sha.w)), 0.f);
    float a4 = fmaxf(fmaxf(fmaf(fx2.x, scb.x, shb.x), fmaf(fn2.x, scb.x, shb.x)), 0.f);
    float a5 = fmaxf(fmaxf(fmaf(fx2.y, scb.y, shb.y), fmaf(fn2.y, scb.y, shb.y)), 0.f);
    float a6 = fmaxf(fmaxf(fmaf(fx3.x, scb.z, shb.z), fmaf(fn3.x, scb.z, shb.z)), 0.f);
    float a7 = fmaxf(fmaxf(fmaf(fx3.y, scb.w, shb.w), fmaf(fn3.y, scb.w, shb.w)), 0.f);

    float* xbase = &g_xsum[(long long)vox * 64 + 8 * l];
    asm volatile("red.global.add.v4.f32 [%0], {%1, %2, %3, %4};"
                 :: "l"(xbase), "f"(a0), "f"(a1), "f"(a2), "f"(a3) : "memory");
    asm volatile("red.global.add.v4.f32 [%0], {%1, %2, %3, %4};"
                 :: "l"(xbase + 4), "f"(a4), "f"(a5), "f"(a6), "f"(a7) : "memory");
    if (l == 0) {
        atomicAdd(&g_cnt[vox], 1.0f);
        atomicAdd(&g_psum[vox * 3 + 0], px);
        atomicAdd(&g_psum[vox * 3 + 1], py);
        atomicAdd(&g_psum[vox * 3 + 2], pz);
    }
}

// -------- finalize output [NVOX, 67]; tail-zero cnt_i for next replay --------
__global__ void out_kernel(float* __restrict__ out) {
    int i = blockIdx.x * blockDim.x + threadIdx.x;
    if (i < NN) g_cnt_i[i] = 0;        // grid 536k threads >= NN
    if (i >= NVOX * 67) return;
    int v = i / 67;
    int c = i - v * 67;
    float denom = fmaxf(g_cnt[v], 1.0f);
    float val = (c < 64) ? g_xsum[v * 64 + c] : g_psum[v * 3 + (c - 64)];
    out[i] = val / denom;
}

extern "C" void kernel_launch(void* const* d_in, const int* in_sizes, int n_in,
                              void* d_out, int out_size) {
    const float* x     = (const float*)d_in[0];  // [N, 64]
    const float* pos   = (const float*)d_in[1];  // [N, 3]
    const int*   ei    = (const int*)d_in[2];    // [2, E]
    const float* W     = (const float*)d_in[3];  // [64, 64]
    const float* b     = (const float*)d_in[4];  // [64]
    const float* gamma = (const float*)d_in[5];  // [64]
    const float* beta  = (const float*)d_in[6];  // [64]
    float* out = (float*)d_out;                  // [8000, 67]

    static cudaStream_t sB = nullptr;
    static cudaEvent_t evFork = nullptr, evJoin = nullptr;
    if (sB == nullptr) {
        cudaStreamCreateWithFlags(&sB, cudaStreamNonBlocking);
        cudaEventCreateWithFlags(&evFork, cudaEventDisableTiming);
        cudaEventCreateWithFlags(&evJoin, cudaEventDisableTiming);
        cudaFuncSetAttribute(gemm_stats_kernel,
                             cudaFuncAttributeMaxDynamicSharedMemorySize, GS_SMEM_BYTES);
    }

    // fork: bucket CSR build (stream B) concurrent with GEMM+stats+scale (stream 0)
    cudaEventRecord(evFork, 0);
    cudaStreamWaitEvent(sB, evFork, 0);

    scatter_kernel<<<EE / 256, 256, 0, sB>>>(ei);                  // 1 (B)
    cudaEventRecord(evJoin, sB);

    gemm_stats_kernel<<<NN / 256, 256, GS_SMEM_BYTES>>>(x, W, b);  // 2 (0)
    scale_kernel<<<1, 64>>>(gamma, beta);                          // 3 (0)

    cudaStreamWaitEvent(0, evJoin, 0);
    gather_kernel<<<NN * 8 / 256, 256>>>(pos);                     // 4 (0) <- ncu capture slot
    out_kernel<<<(NVOX * 67 + 255) / 256, 256>>>(out);             // 5 (0)
}

// round 8
// speedup vs baseline: 5.8218x; 1.2165x over previous
#include <cuda_runtime.h>
#include <cuda_fp16.h>
#include <mma.h>
#include <stdint.h>

using namespace nvcuda;

// Problem constants
#define NN 262144
#define EE (NN * 16)
#define CC 64
#define NVOXD 20
#define NVOX 8000
#define BN_EPS 1e-5f
#define GRID_INV 2.0f   // 1/0.5
#define FULLMASK 0xFFFFFFFFu
#define MAXDEG 64

typedef unsigned long long ull;
typedef long long ll;

// -------- scratch --------
__device__ __half g_hh[NN * CC];          // h = x@W+b in fp16
__device__ float g_colsum[CC];
__device__ float g_colsq[CC];
__device__ float g_scale[CC];
__device__ float g_shift[CC];
__device__ int   g_negflag;               // any(scale<0)?
__device__ float g_xsum[NVOX * CC];
__device__ float g_psum[NVOX * 3];
__device__ float g_cnt[NVOX];
__device__ int   g_cnt_i[NN];             // in-degree (zeroed by prev call's out_kernel / load-time)
__device__ int   g_adj[NN * MAXDEG];      // fixed-capacity per-node buckets

// ======================= STREAM A: wmma GEMM + stats (fp16 out) =======================
// 128 rows/block, 256 threads (8 warps). Warp w computes rows 16w..16w+15 x all 64 cols
// with m16n16k16 HMMA, fp32 accum. C staged in smem, bias added, converted to fp16,
// column stats reduced from the same pass.
#define XS 80                 // half stride for x tile (160B rows: 32B-aligned)
#define WS 80                 // half stride for W tile
#define CSO 72                // float stride for C tile (288B rows: 32B-aligned)
#define SM_X_BYTES (128 * XS * 2)          // 20480
#define SM_W_OFF   SM_X_BYTES              // W at 20480 (32B aligned)
#define SM_C_BYTES (128 * CSO * 4)         // 36864 (overlaps x+W region)
#define SM_RED_OFF SM_C_BYTES              // 128 floats of reduction space
#define GS_SMEM_BYTES (SM_C_BYTES + 512)

__global__ __launch_bounds__(256) void gemm_stats_kernel(const float* __restrict__ x,
                                                         const float* __restrict__ W,
                                                         const float* __restrict__ b) {
    extern __shared__ char smc[];
    __half* xs  = reinterpret_cast<__half*>(smc);
    __half* Wsf = reinterpret_cast<__half*>(smc + SM_W_OFF);
    float*  Cs  = reinterpret_cast<float*>(smc);
    float*  red = reinterpret_cast<float*>(smc + SM_RED_OFF);   // [64] sum | [64] sq
    int tid = threadIdx.x;
    int row0 = blockIdx.x * 128;

    // load + convert x tile (128x64 fp32 -> fp16)
#pragma unroll
    for (int i = tid; i < 2048; i += 256) {               // 2048 float4 = 8192 elems
        int row = i >> 4, c4 = (i & 15) * 4;
        float4 v = reinterpret_cast<const float4*>(x + (ll)(row0 + row) * 64)[i & 15];
        __half2 lo = __floats2half2_rn(v.x, v.y);
        __half2 hi = __floats2half2_rn(v.z, v.w);
        uint2 p;
        p.x = *reinterpret_cast<unsigned*>(&lo);
        p.y = *reinterpret_cast<unsigned*>(&hi);
        *reinterpret_cast<uint2*>(&xs[row * XS + c4]) = p;
    }
    // load + convert W (64x64)
#pragma unroll
    for (int i = tid; i < 1024; i += 256) {
        int row = i >> 4, c4 = (i & 15) * 4;
        float4 v = reinterpret_cast<const float4*>(W)[i];
        __half2 lo = __floats2half2_rn(v.x, v.y);
        __half2 hi = __floats2half2_rn(v.z, v.w);
        uint2 p;
        p.x = *reinterpret_cast<unsigned*>(&lo);
        p.y = *reinterpret_cast<unsigned*>(&hi);
        *reinterpret_cast<uint2*>(&Wsf[row * WS + c4]) = p;
    }
    __syncthreads();

    int w = tid >> 5;
    wmma::fragment<wmma::accumulator, 16, 16, 16, float> acc[4];
#pragma unroll
    for (int n = 0; n < 4; n++) wmma::fill_fragment(acc[n], 0.0f);
#pragma unroll
    for (int k = 0; k < 4; k++) {
        wmma::fragment<wmma::matrix_a, 16, 16, 16, __half, wmma::row_major> af;
        wmma::load_matrix_sync(af, xs + (16 * w) * XS + 16 * k, XS);
#pragma unroll
        for (int n = 0; n < 4; n++) {
            wmma::fragment<wmma::matrix_b, 16, 16, 16, __half, wmma::row_major> bf;
            wmma::load_matrix_sync(bf, Wsf + (16 * k) * WS + 16 * n, WS);
            wmma::mma_sync(acc[n], af, bf, acc[n]);
        }
    }
    __syncthreads();   // all smem reads done; Cs overlaps xs/Wsf

#pragma unroll
    for (int n = 0; n < 4; n++)
        wmma::store_matrix_sync(Cs + (16 * w) * CSO + 16 * n, acc[n], CSO, wmma::mem_row_major);
    if (tid < 128) red[tid] = 0.f;
    __syncthreads();

    // bias + fp16 convert + column stats. thread: colpair cp=tid&31, rowgroup rg=tid>>5 (16 rows)
    int cp = tid & 31;
    int rg = tid >> 5;
    float b0 = b[2 * cp], b1 = b[2 * cp + 1];
    float s0 = 0.f, q0 = 0.f, s1 = 0.f, q1 = 0.f;
    unsigned* hout = reinterpret_cast<unsigned*>(g_hh);
#pragma unroll
    for (int rr = 0; rr < 16; rr++) {
        int row = 16 * rg + rr;
        float2 v = *reinterpret_cast<float2*>(&Cs[row * CSO + 2 * cp]);
        float v0 = v.x + b0, v1 = v.y + b1;
        __half2 h2 = __floats2half2_rn(v0, v1);
        hout[(ll)(row0 + row) * 32 + cp] = *reinterpret_cast<unsigned*>(&h2);
        s0 += v0; q0 += v0 * v0; s1 += v1; q1 += v1 * v1;
    }
    atomicAdd(&red[2 * cp], s0);      atomicAdd(&red[2 * cp + 1], s1);
    atomicAdd(&red[64 + 2 * cp], q0); atomicAdd(&red[64 + 2 * cp + 1], q1);
    __syncthreads();
    if (tid < 64) {
        atomicAdd(&g_colsum[tid], red[tid]);
        atomicAdd(&g_colsq[tid],  red[64 + tid]);
    }
}

// -------- A2: fold BN into scale/shift; detect negative scales; reset stats --------
__global__ void scale_kernel(const float* __restrict__ gamma, const float* __restrict__ beta) {
    __shared__ int flag;
    int c = threadIdx.x;
    if (c == 0) flag = 0;
    __syncthreads();
    if (c < CC) {
        float mean = g_colsum[c] * (1.0f / NN);
        float var = g_colsq[c] * (1.0f / NN) - mean * mean;
        float sc = gamma[c] * rsqrtf(var + BN_EPS);
        g_scale[c] = sc;
        g_shift[c] = beta[c] - mean * sc;
        g_colsum[c] = 0.f;
        g_colsq[c] = 0.f;
        if (sc < 0.f) flag = 1;
    }
    __syncthreads();
    if (c == 0) g_negflag = flag;
}

// ================= STREAM B: single-kernel bucket CSR build (+zero acc) =================
__global__ __launch_bounds__(256) void scatter_kernel(const int* __restrict__ ei) {
    int e = blockIdx.x * blockDim.x + threadIdx.x;   // grid covers EE exactly
    if (e < NVOX * CC) g_xsum[e] = 0.f;
    if (e < NVOX * 3)  g_psum[e] = 0.f;
    if (e < NVOX)      g_cnt[e]  = 0.f;
    int row = ei[e];
    int col = ei[EE + e];
    int p = atomicAdd(&g_cnt_i[col], 1);
    if (p < MAXDEG) g_adj[col * MAXDEG + p] = row;
}

// ======================= JOINED: gather (fp16 max) -> out =======================
// 8 lanes per node; lane handles 8 channels (uint4). Neighbor indices come from
// uniform int4 loads (no shfl), prefetched one chunk ahead. Fast path (all BN
// scales > 0) tracks only the max; slow path tracks max+min.
__global__ __launch_bounds__(256) void gather_kernel(const float* __restrict__ pos) {
    int node = (blockIdx.x * blockDim.x + threadIdx.x) >> 3;
    int l = threadIdx.x & 7;
    int base8 = threadIdx.x & 24;
    unsigned int m8 = 0xFFu << base8;

    int cnt = min(g_cnt_i[node], MAXDEG);
    const int4* bucket4 = reinterpret_cast<const int4*>(&g_adj[(ll)node * MAXDEG]);
    float px = 0.f, py = 0.f, pz = 0.f;
    if (l == 0) {
        px = pos[node * 3 + 0];
        py = pos[node * 3 + 1];
        pz = pos[node * 3 + 2];
    }
    const uint4* h8 = reinterpret_cast<const uint4*>(g_hh);
    uint4 self = __ldg(&h8[(ll)node * 8 + l]);

    __half2 mx0 = *reinterpret_cast<__half2*>(&self.x);
    __half2 mx1 = *reinterpret_cast<__half2*>(&self.y);
    __half2 mx2 = *reinterpret_cast<__half2*>(&self.z);
    __half2 mx3 = *reinterpret_cast<__half2*>(&self.w);
    __half2 mn0 = mx0, mn1 = mx1, mn2 = mx2, mn3 = mx3;

    int vox = 0;
    if (l == 0) {
        int vx = min(max((int)floorf(px * GRID_INV), 0), NVOXD - 1);
        int vy = min(max((int)floorf(py * GRID_INV), 0), NVOXD - 1);
        int vz = min(max((int)floorf(pz * GRID_INV), 0), NVOXD - 1);
        vox = (vx * NVOXD + vy) * NVOXD + vz;
    }
    vox = __shfl_sync(m8, vox, base8);

    int neg = g_negflag;
    int nb4 = (cnt + 3) >> 2;
    int4 q = (nb4 > 0) ? __ldg(&bucket4[0]) : make_int4(node, node, node, node);

#define GATH_BODY(DOMIN)                                                        \
    for (int c = 0; c < nb4; c++) {                                             \
        int4 qn = (c + 1 < nb4) ? __ldg(&bucket4[c + 1]) : q;                   \
        int j0 = 4 * c;                                                         \
        int s0 = (j0 + 0 < cnt) ? q.x : node;                                   \
        int s1 = (j0 + 1 < cnt) ? q.y : node;                                   \
        int s2 = (j0 + 2 < cnt) ? q.z : node;                                   \
        int s3 = (j0 + 3 < cnt) ? q.w : node;                                   \
        uint4 u0 = __ldg(&h8[(ll)s0 * 8 + l]);                                  \
        uint4 u1 = __ldg(&h8[(ll)s1 * 8 + l]);                                  \
        uint4 u2 = __ldg(&h8[(ll)s2 * 8 + l]);                                  \
        uint4 u3 = __ldg(&h8[(ll)s3 * 8 + l]);                                  \
        const uint4* us[4] = {&u0, &u1, &u2, &u3};                              \
        _Pragma("unroll")                                                       \
        for (int t = 0; t < 4; t++) {                                           \
            __half2 a0 = *reinterpret_cast<const __half2*>(&us[t]->x);          \
            __half2 a1 = *reinterpret_cast<const __half2*>(&us[t]->y);          \
            __half2 a2 = *reinterpret_cast<const __half2*>(&us[t]->z);          \
            __half2 a3 = *reinterpret_cast<const __half2*>(&us[t]->w);          \
            mx0 = __hmax2(mx0, a0); mx1 = __hmax2(mx1, a1);                     \
            mx2 = __hmax2(mx2, a2); mx3 = __hmax2(mx3, a3);                     \
            if (DOMIN) {                                                        \
                mn0 = __hmin2(mn0, a0); mn1 = __hmin2(mn1, a1);                 \
                mn2 = __hmin2(mn2, a2); mn3 = __hmin2(mn3, a3);                 \
            }                                                                   \
        }                                                                       \
        q = qn;                                                                 \
    }

    if (!neg) { GATH_BODY(0) } else { GATH_BODY(1) }
#undef GATH_BODY

    float4 sca = *reinterpret_cast<const float4*>(&g_scale[8 * l]);
    float4 scb = *reinterpret_cast<const float4*>(&g_scale[8 * l + 4]);
    float4 sha = *reinterpret_cast<const float4*>(&g_shift[8 * l]);
    float4 shb = *reinterpret_cast<const float4*>(&g_shift[8 * l + 4]);

    float2 fx0 = __half22float2(mx0), fx1 = __half22float2(mx1);
    float2 fx2 = __half22float2(mx2), fx3 = __half22float2(mx3);

    float a0, a1, a2, a3, a4, a5, a6, a7;
    if (!neg) {
        a0 = fmaxf(fmaf(fx0.x, sca.x, sha.x), 0.f);
        a1 = fmaxf(fmaf(fx0.y, sca.y, sha.y), 0.f);
        a2 = fmaxf(fmaf(fx1.x, sca.z, sha.z), 0.f);
        a3 = fmaxf(fmaf(fx1.y, sca.w, sha.w), 0.f);
        a4 = fmaxf(fmaf(fx2.x, scb.x, shb.x), 0.f);
        a5 = fmaxf(fmaf(fx2.y, scb.y, shb.y), 0.f);
        a6 = fmaxf(fmaf(fx3.x, scb.z, shb.z), 0.f);
        a7 = fmaxf(fmaf(fx3.y, scb.w, shb.w), 0.f);
    } else {
        float2 fn0 = __half22float2(mn0), fn1 = __half22float2(mn1);
        float2 fn2 = __half22float2(mn2), fn3 = __half22float2(mn3);
        a0 = fmaxf(fmaxf(fmaf(fx0.x, sca.x, sha.x), fmaf(fn0.x, sca.x, sha.x)), 0.f);
        a1 = fmaxf(fmaxf(fmaf(fx0.y, sca.y, sha.y), fmaf(fn0.y, sca.y, sha.y)), 0.f);
        a2 = fmaxf(fmaxf(fmaf(fx1.x, sca.z, sha.z), fmaf(fn1.x, sca.z, sha.z)), 0.f);
        a3 = fmaxf(fmaxf(fmaf(fx1.y, sca.w, sha.w), fmaf(fn1.y, sca.w, sha.w)), 0.f);
        a4 = fmaxf(fmaxf(fmaf(fx2.x, scb.x, shb.x), fmaf(fn2.x, scb.x, shb.x)), 0.f);
        a5 = fmaxf(fmaxf(fmaf(fx2.y, scb.y, shb.y), fmaf(fn2.y, scb.y, shb.y)), 0.f);
        a6 = fmaxf(fmaxf(fmaf(fx3.x, scb.z, shb.z), fmaf(fn3.x, scb.z, shb.z)), 0.f);
        a7 = fmaxf(fmaxf(fmaf(fx3.y, scb.w, shb.w), fmaf(fn3.y, scb.w, shb.w)), 0.f);
    }

    float* xbase = &g_xsum[(ll)vox * 64 + 8 * l];
    asm volatile("red.global.add.v4.f32 [%0], {%1, %2, %3, %4};"
                 :: "l"(xbase), "f"(a0), "f"(a1), "f"(a2), "f"(a3) : "memory");
    asm volatile("red.global.add.v4.f32 [%0], {%1, %2, %3, %4};"
                 :: "l"(xbase + 4), "f"(a4), "f"(a5), "f"(a6), "f"(a7) : "memory");
    if (l == 0) {
        atomicAdd(&g_cnt[vox], 1.0f);
        atomicAdd(&g_psum[vox * 3 + 0], px);
        atomicAdd(&g_psum[vox * 3 + 1], py);
        atomicAdd(&g_psum[vox * 3 + 2], pz);
    }
}

// -------- finalize output [NVOX, 67]; tail-zero cnt_i for next replay --------
__global__ void out_kernel(float* __restrict__ out) {
    int i = blockIdx.x * blockDim.x + threadIdx.x;
    if (i < NN) g_cnt_i[i] = 0;        // grid 536k threads >= NN
    if (i >= NVOX * 67) return;
    int v = i / 67;
    int c = i - v * 67;
    float denom = fmaxf(g_cnt[v], 1.0f);
    float val = (c < 64) ? g_xsum[v * 64 + c] : g_psum[v * 3 + (c - 64)];
    out[i] = val / denom;
}

extern "C" void kernel_launch(void* const* d_in, const int* in_sizes, int n_in,
                              void* d_out, int out_size) {
    const float* x     = (const float*)d_in[0];  // [N, 64]
    const float* pos   = (const float*)d_in[1];  // [N, 3]
    const int*   ei    = (const int*)d_in[2];    // [2, E]
    const float* W     = (const float*)d_in[3];  // [64, 64]
    const float* b     = (const float*)d_in[4];  // [64]
    const float* gamma = (const float*)d_in[5];  // [64]
    const float* beta  = (const float*)d_in[6];  // [64]
    float* out = (float*)d_out;                  // [8000, 67]

    static cudaStream_t sB = nullptr;
    static cudaEvent_t evFork = nullptr, evJoin = nullptr;
    if (sB == nullptr) {
        cudaStreamCreateWithFlags(&sB, cudaStreamNonBlocking);
        cudaEventCreateWithFlags(&evFork, cudaEventDisableTiming);
        cudaEventCreateWithFlags(&evJoin, cudaEventDisableTiming);
    }

    // fork: bucket CSR build (stream B) concurrent with wmma GEMM+stats+scale (stream 0)
    cudaEventRecord(evFork, 0);
    cudaStreamWaitEvent(sB, evFork, 0);

    scatter_kernel<<<EE / 256, 256, 0, sB>>>(ei);                  // 1 (B)
    cudaEventRecord(evJoin, sB);

    gemm_stats_kernel<<<NN / 128, 256, GS_SMEM_BYTES>>>(x, W, b);  // 2 (0)
    scale_kernel<<<1, 64>>>(gamma, beta);                          // 3 (0)

    cudaStreamWaitEvent(0, evJoin, 0);
    gather_kernel<<<NN * 8 / 256, 256>>>(pos);                     // 4 (0) <- ncu capture slot
    out_kernel<<<(NVOX * 67 + 255) / 256, 256>>>(out);             // 5 (0)
}